// round 1
// baseline (speedup 1.0000x reference)
#include <cuda_runtime.h>
#include <math.h>

// Problem constants (Mixtral sparse MoE block)
#define NT 4096   // tokens
#define NH 2048   // hidden
#define NF 8192   // ffn dim
#define NE 8      // experts
#define TOPK 2

#define BM 64
#define BN 64
#define BK 32
#define NSLOT (TOPK*NT)                 // 8192 (token, k) slots, always exact
#define MAX_TILES (NSLOT/BM + NE)       // 136 (padding: <= +1 tile per expert)
#define MAX_SLOTS (MAX_TILES*BM)        // 8704

// ---------------- device scratch (no allocations allowed) ----------------
__device__ int   g_cnt[NE];
__device__ int   g_cursor[NE];
__device__ int   g_off[NE+1];
__device__ int   g_tok_expert[NSLOT];
__device__ float g_tok_weight[NSLOT];
__device__ int   g_slot_token[MAX_SLOTS];
__device__ float g_slot_weight[MAX_SLOTS];
__device__ int   g_tile_expert[MAX_TILES];
__device__ float g_hh[(size_t)MAX_SLOTS * NF];   // SwiGLU intermediate, ~285 MB

// ---------------- packed f32x2 helpers (PTX-only on Blackwell) ----------------
__device__ __forceinline__ void fma2(unsigned long long &d, unsigned long long a,
                                     unsigned long long b) {
    asm("fma.rn.f32x2 %0, %1, %2, %0;" : "+l"(d) : "l"(a), "l"(b));
}
__device__ __forceinline__ unsigned long long pack2(float v) {
    unsigned long long r;
    asm("mov.b64 %0, {%1, %2};" : "=l"(r) : "f"(v), "f"(v));
    return r;
}
__device__ __forceinline__ float2 unpack2(unsigned long long v) {
    float2 r;
    asm("mov.b64 {%0, %1}, %2;" : "=f"(r.x), "=f"(r.y) : "l"(v));
    return r;
}

// ---------------- stage 0: zero output + expert counters ----------------
__global__ void k_zero(float* __restrict__ out, int n) {
    int i = blockIdx.x * blockDim.x + threadIdx.x;
    if (i < n) out[i] = 0.f;
    if (blockIdx.x == 0 && threadIdx.x < NE) g_cnt[threadIdx.x] = 0;
}

// ---------------- stage 1: router (logits -> top2 -> renorm weights) ----------------
__global__ void k_router(const float* __restrict__ x, const float* __restrict__ gw) {
    const int t   = blockIdx.x;
    const int tid = threadIdx.x;
    float acc[NE];
#pragma unroll
    for (int e = 0; e < NE; e++) acc[e] = 0.f;
    const float* xr = x + (size_t)t * NH;
    for (int h = tid; h < NH; h += 256) {
        float xv = xr[h];
#pragma unroll
        for (int e = 0; e < NE; e++) acc[e] += xv * gw[e * NH + h];
    }
    __shared__ float part[NE][256];
#pragma unroll
    for (int e = 0; e < NE; e++) part[e][tid] = acc[e];
    __syncthreads();
    if (tid < NE) {
        float s = 0.f;
        for (int i = 0; i < 256; i++) s += part[tid][i];
        part[tid][0] = s;
    }
    __syncthreads();
    if (tid == 0) {
        float l[NE];
#pragma unroll
        for (int e = 0; e < NE; e++) l[e] = part[e][0];
        int i0 = 0;
#pragma unroll
        for (int e = 1; e < NE; e++) if (l[e] > l[i0]) i0 = e;
        int i1 = -1;
#pragma unroll
        for (int e = 0; e < NE; e++)
            if (e != i0 && (i1 < 0 || l[e] > l[i1])) i1 = e;
        // renormalized top-2 softmax: w0 = e^l0/(e^l0+e^l1)
        float w0 = 1.f / (1.f + expf(l[i1] - l[i0]));
        g_tok_expert[2 * t]     = i0;
        g_tok_expert[2 * t + 1] = i1;
        g_tok_weight[2 * t]     = w0;
        g_tok_weight[2 * t + 1] = 1.f - w0;
        atomicAdd(&g_cnt[i0], 1);
        atomicAdd(&g_cnt[i1], 1);
    }
}

// ---------------- stage 2: padded offsets, tile->expert map, slot init ----------------
__global__ void k_setup() {
    __shared__ int soff[NE + 1];
    const int tid = threadIdx.x;
    if (tid == 0) {
        int o = 0;
        for (int e = 0; e < NE; e++) {
            soff[e] = o; g_off[e] = o; g_cursor[e] = 0;
            o += ((g_cnt[e] + BM - 1) / BM) * BM;   // pad each segment to BM
        }
        soff[NE] = o; g_off[NE] = o;
    }
    __syncthreads();
    const int ntiles = soff[NE] / BM;
    for (int i = tid; i < MAX_TILES; i += blockDim.x) {
        int ex = -1;
        if (i < ntiles) {
            int r = i * BM;
            for (int e = 0; e < NE; e++)
                if (r >= soff[e] && r < soff[e + 1]) ex = e;
        }
        g_tile_expert[i] = ex;
    }
    for (int i = tid; i < MAX_SLOTS; i += blockDim.x) {
        g_slot_token[i]  = -1;
        g_slot_weight[i] = 0.f;
    }
}

// ---------------- stage 3: scatter (token,k) -> expert slot lists ----------------
__global__ void k_scatter() {
    int i = blockIdx.x * blockDim.x + threadIdx.x;
    if (i >= NSLOT) return;
    int e   = g_tok_expert[i];
    int pos = atomicAdd(&g_cursor[e], 1);
    int s   = g_off[e] + pos;
    g_slot_token[s]  = i >> 1;          // token id
    g_slot_weight[s] = g_tok_weight[i];
}

// ---------------- stage 4: hh = silu(X W1^T) * (X W3^T), grouped per expert ----------------
__global__ __launch_bounds__(256, 2)
void k_gemm1(const float* __restrict__ x, const float* __restrict__ w1,
             const float* __restrict__ w3) {
    const int e = g_tile_expert[blockIdx.y];
    if (e < 0) return;
    const int r0  = blockIdx.y * BM;
    const int f0  = blockIdx.x * BN;
    const int tid = threadIdx.x;

    __shared__ float Xs[BK][BM];
    __shared__ float W1s[BK][BN];
    __shared__ float W3s[BK][BN];
    __shared__ int   toks[BM];

    if (tid < BM) toks[tid] = g_slot_token[r0 + tid];
    __syncthreads();

    // loader mapping: 64 rows x 32 floats per tile = 512 float4; 2 per thread
    const int row0 = tid >> 3;            // 0..31
    const int row1 = row0 + 32;           // 32..63
    const int kq0  = (tid & 7) * 4;       // 0..28

    const int t0 = toks[row0];
    const int t1 = toks[row1];
    const float* x0  = x + (size_t)(t0 >= 0 ? t0 : 0) * NH + kq0;
    const float* x1  = x + (size_t)(t1 >= 0 ? t1 : 0) * NH + kq0;
    const float* w1a = w1 + ((size_t)e * NF + f0 + row0) * NH + kq0;
    const float* w1b = w1 + ((size_t)e * NF + f0 + row1) * NH + kq0;
    const float* w3a = w3 + ((size_t)e * NF + f0 + row0) * NH + kq0;
    const float* w3b = w3 + ((size_t)e * NF + f0 + row1) * NH + kq0;

    unsigned long long acc1[4][2] = {};
    unsigned long long acc3[4][2] = {};
    const int ty = tid >> 4, tx = tid & 15;

    for (int k0 = 0; k0 < NH; k0 += BK) {
        float4 xv0 = (t0 >= 0) ? *(const float4*)x0 : make_float4(0.f, 0.f, 0.f, 0.f);
        float4 xv1 = (t1 >= 0) ? *(const float4*)x1 : make_float4(0.f, 0.f, 0.f, 0.f);
        float4 u0 = *(const float4*)w1a;
        float4 u1 = *(const float4*)w1b;
        float4 v0 = *(const float4*)w3a;
        float4 v1 = *(const float4*)w3b;
        __syncthreads();
        Xs[kq0 + 0][row0] = xv0.x; Xs[kq0 + 1][row0] = xv0.y;
        Xs[kq0 + 2][row0] = xv0.z; Xs[kq0 + 3][row0] = xv0.w;
        Xs[kq0 + 0][row1] = xv1.x; Xs[kq0 + 1][row1] = xv1.y;
        Xs[kq0 + 2][row1] = xv1.z; Xs[kq0 + 3][row1] = xv1.w;
        W1s[kq0 + 0][row0] = u0.x; W1s[kq0 + 1][row0] = u0.y;
        W1s[kq0 + 2][row0] = u0.z; W1s[kq0 + 3][row0] = u0.w;
        W1s[kq0 + 0][row1] = u1.x; W1s[kq0 + 1][row1] = u1.y;
        W1s[kq0 + 2][row1] = u1.z; W1s[kq0 + 3][row1] = u1.w;
        W3s[kq0 + 0][row0] = v0.x; W3s[kq0 + 1][row0] = v0.y;
        W3s[kq0 + 2][row0] = v0.z; W3s[kq0 + 3][row0] = v0.w;
        W3s[kq0 + 0][row1] = v1.x; W3s[kq0 + 1][row1] = v1.y;
        W3s[kq0 + 2][row1] = v1.z; W3s[kq0 + 3][row1] = v1.w;
        __syncthreads();
        x0 += BK; x1 += BK; w1a += BK; w1b += BK; w3a += BK; w3b += BK;

#pragma unroll
        for (int kk = 0; kk < BK; kk++) {
            float4 av = *(const float4*)&Xs[kk][ty * 4];
            unsigned long long p0 = pack2(av.x), p1 = pack2(av.y);
            unsigned long long p2 = pack2(av.z), p3 = pack2(av.w);
            ulonglong2 b1 = *(const ulonglong2*)&W1s[kk][tx * 4];
            ulonglong2 b3 = *(const ulonglong2*)&W3s[kk][tx * 4];
            fma2(acc1[0][0], p0, b1.x); fma2(acc1[0][1], p0, b1.y);
            fma2(acc1[1][0], p1, b1.x); fma2(acc1[1][1], p1, b1.y);
            fma2(acc1[2][0], p2, b1.x); fma2(acc1[2][1], p2, b1.y);
            fma2(acc1[3][0], p3, b1.x); fma2(acc1[3][1], p3, b1.y);
            fma2(acc3[0][0], p0, b3.x); fma2(acc3[0][1], p0, b3.y);
            fma2(acc3[1][0], p1, b3.x); fma2(acc3[1][1], p1, b3.y);
            fma2(acc3[2][0], p2, b3.x); fma2(acc3[2][1], p2, b3.y);
            fma2(acc3[3][0], p3, b3.x); fma2(acc3[3][1], p3, b3.y);
        }
    }

    // epilogue: SwiGLU, write hh (padded rows produce exact zeros)
#pragma unroll
    for (int i = 0; i < 4; i++) {
        const int r = r0 + ty * 4 + i;
        float* hp = g_hh + (size_t)r * NF + f0 + tx * 4;
#pragma unroll
        for (int jp = 0; jp < 2; jp++) {
            float2 a = unpack2(acc1[i][jp]);
            float2 b = unpack2(acc3[i][jp]);
            float h0 = (a.x / (1.f + expf(-a.x))) * b.x;
            float h1 = (a.y / (1.f + expf(-a.y))) * b.y;
            hp[jp * 2 + 0] = h0;
            hp[jp * 2 + 1] = h1;
        }
    }
}

// ---------------- stage 5: y = hh W2^T, weighted scatter-add to out ----------------
__global__ __launch_bounds__(256, 2)
void k_gemm2(const float* __restrict__ w2, float* __restrict__ out) {
    const int e = g_tile_expert[blockIdx.y];
    if (e < 0) return;
    const int r0  = blockIdx.y * BM;
    const int h0  = blockIdx.x * BN;
    const int tid = threadIdx.x;

    __shared__ float Hs[BK][BM];
    __shared__ float W2s[BK][BN];
    __shared__ int   toks[BM];
    __shared__ float wgts[BM];

    if (tid < BM) {
        toks[tid] = g_slot_token[r0 + tid];
        wgts[tid] = g_slot_weight[r0 + tid];
    }
    __syncthreads();

    const int row0 = tid >> 3;
    const int row1 = row0 + 32;
    const int kq0  = (tid & 7) * 4;

    const float* ha = g_hh + (size_t)(r0 + row0) * NF + kq0;
    const float* hb = g_hh + (size_t)(r0 + row1) * NF + kq0;
    const float* wa = w2 + ((size_t)e * NH + h0 + row0) * NF + kq0;
    const float* wb = w2 + ((size_t)e * NH + h0 + row1) * NF + kq0;

    unsigned long long acc[4][2] = {};
    const int ty = tid >> 4, tx = tid & 15;

    for (int k0 = 0; k0 < NF; k0 += BK) {
        float4 hv0 = *(const float4*)ha;
        float4 hv1 = *(const float4*)hb;
        float4 wv0 = *(const float4*)wa;
        float4 wv1 = *(const float4*)wb;
        __syncthreads();
        Hs[kq0 + 0][row0] = hv0.x; Hs[kq0 + 1][row0] = hv0.y;
        Hs[kq0 + 2][row0] = hv0.z; Hs[kq0 + 3][row0] = hv0.w;
        Hs[kq0 + 0][row1] = hv1.x; Hs[kq0 + 1][row1] = hv1.y;
        Hs[kq0 + 2][row1] = hv1.z; Hs[kq0 + 3][row1] = hv1.w;
        W2s[kq0 + 0][row0] = wv0.x; W2s[kq0 + 1][row0] = wv0.y;
        W2s[kq0 + 2][row0] = wv0.z; W2s[kq0 + 3][row0] = wv0.w;
        W2s[kq0 + 0][row1] = wv1.x; W2s[kq0 + 1][row1] = wv1.y;
        W2s[kq0 + 2][row1] = wv1.z; W2s[kq0 + 3][row1] = wv1.w;
        __syncthreads();
        ha += BK; hb += BK; wa += BK; wb += BK;

#pragma unroll
        for (int kk = 0; kk < BK; kk++) {
            float4 av = *(const float4*)&Hs[kk][ty * 4];
            unsigned long long p0 = pack2(av.x), p1 = pack2(av.y);
            unsigned long long p2 = pack2(av.z), p3 = pack2(av.w);
            ulonglong2 b = *(const ulonglong2*)&W2s[kk][tx * 4];
            fma2(acc[0][0], p0, b.x); fma2(acc[0][1], p0, b.y);
            fma2(acc[1][0], p1, b.x); fma2(acc[1][1], p1, b.y);
            fma2(acc[2][0], p2, b.x); fma2(acc[2][1], p2, b.y);
            fma2(acc[3][0], p3, b.x); fma2(acc[3][1], p3, b.y);
        }
    }

#pragma unroll
    for (int i = 0; i < 4; i++) {
        const int rl = ty * 4 + i;
        const int t  = toks[rl];
        if (t < 0) continue;
        const float w = wgts[rl];
        float* op = out + (size_t)t * NH + h0 + tx * 4;
#pragma unroll
        for (int jp = 0; jp < 2; jp++) {
            float2 v = unpack2(acc[i][jp]);
            atomicAdd(&op[jp * 2 + 0], w * v.x);  // exactly 2 adds/elem -> commutative
            atomicAdd(&op[jp * 2 + 1], w * v.y);  // -> bitwise deterministic
        }
    }
}

// ---------------- launch ----------------
extern "C" void kernel_launch(void* const* d_in, const int* in_sizes, int n_in,
                              void* d_out, int out_size) {
    const float* x  = (const float*)d_in[0];   // hidden_states [T,H]
    const float* gw = (const float*)d_in[1];   // gate_w        [E,H]
    const float* w1 = (const float*)d_in[2];   // w1            [E,F,H]
    const float* w2 = (const float*)d_in[3];   // w2            [E,H,F]
    const float* w3 = (const float*)d_in[4];   // w3            [E,F,H]
    float* out = (float*)d_out;

    const int n = NT * NH;
    k_zero<<<(n + 255) / 256, 256>>>(out, n);
    k_router<<<NT, 256>>>(x, gw);
    k_setup<<<1, 256>>>();
    k_scatter<<<(NSLOT + 255) / 256, 256>>>();
    k_gemm1<<<dim3(NF / BN, MAX_TILES), 256>>>(x, w1, w3);
    k_gemm2<<<dim3(NH / BN, MAX_TILES), 256>>>(w2, out);
}

// round 2
// speedup vs baseline: 1.0004x; 1.0004x over previous
#include <cuda_runtime.h>
#include <math.h>

// Problem constants (Mixtral sparse MoE block)
#define NT 4096   // tokens
#define NH 2048   // hidden
#define NF 8192   // ffn dim
#define NE 8      // experts
#define TOPK 2

#define BM 64
#define BN 64
#define BK 32
#define NSLOT (TOPK*NT)                 // 8192 (token, k) slots, always exact
#define MAX_TILES (NSLOT/BM + NE)       // 136 (padding: <= +1 tile per expert)
#define MAX_SLOTS (MAX_TILES*BM)        // 8704

// ---------------- device scratch (no allocations allowed) ----------------
__device__ int   g_cnt[NE];
__device__ int   g_cursor[NE];
__device__ int   g_off[NE+1];
__device__ int   g_tok_expert[NSLOT];
__device__ float g_tok_weight[NSLOT];
__device__ int   g_slot_token[MAX_SLOTS];
__device__ float g_slot_weight[MAX_SLOTS];
__device__ int   g_tile_expert[MAX_TILES];
__device__ float g_hh[(size_t)MAX_SLOTS * NF];   // SwiGLU intermediate, ~285 MB

// ---------------- packed f32x2 helpers (PTX-only on Blackwell) ----------------
__device__ __forceinline__ void fma2(unsigned long long &d, unsigned long long a,
                                     unsigned long long b) {
    asm("fma.rn.f32x2 %0, %1, %2, %0;" : "+l"(d) : "l"(a), "l"(b));
}
__device__ __forceinline__ unsigned long long pack2(float v) {
    unsigned long long r;
    asm("mov.b64 %0, {%1, %2};" : "=l"(r) : "f"(v), "f"(v));
    return r;
}
__device__ __forceinline__ float2 unpack2(unsigned long long v) {
    float2 r;
    asm("mov.b64 {%0, %1}, %2;" : "=f"(r.x), "=f"(r.y) : "l"(v));
    return r;
}

// ---------------- stage 0: zero output + expert counters ----------------
__global__ void k_zero(float* __restrict__ out, int n) {
    int i = blockIdx.x * blockDim.x + threadIdx.x;
    if (i < n) out[i] = 0.f;
    if (blockIdx.x == 0 && threadIdx.x < NE) g_cnt[threadIdx.x] = 0;
}

// ---------------- stage 1: router (logits -> top2 -> renorm weights) ----------------
__global__ void k_router(const float* __restrict__ x, const float* __restrict__ gw) {
    const int t   = blockIdx.x;
    const int tid = threadIdx.x;
    float acc[NE];
#pragma unroll
    for (int e = 0; e < NE; e++) acc[e] = 0.f;
    const float* xr = x + (size_t)t * NH;
    for (int h = tid; h < NH; h += 256) {
        float xv = xr[h];
#pragma unroll
        for (int e = 0; e < NE; e++) acc[e] += xv * gw[e * NH + h];
    }
    __shared__ float part[NE][256];
#pragma unroll
    for (int e = 0; e < NE; e++) part[e][tid] = acc[e];
    __syncthreads();
    if (tid < NE) {
        float s = 0.f;
        for (int i = 0; i < 256; i++) s += part[tid][i];
        part[tid][0] = s;
    }
    __syncthreads();
    if (tid == 0) {
        float l[NE];
#pragma unroll
        for (int e = 0; e < NE; e++) l[e] = part[e][0];
        int i0 = 0;
#pragma unroll
        for (int e = 1; e < NE; e++) if (l[e] > l[i0]) i0 = e;
        int i1 = -1;
#pragma unroll
        for (int e = 0; e < NE; e++)
            if (e != i0 && (i1 < 0 || l[e] > l[i1])) i1 = e;
        // renormalized top-2 softmax: w0 = e^l0/(e^l0+e^l1)
        float w0 = 1.f / (1.f + expf(l[i1] - l[i0]));
        g_tok_expert[2 * t]     = i0;
        g_tok_expert[2 * t + 1] = i1;
        g_tok_weight[2 * t]     = w0;
        g_tok_weight[2 * t + 1] = 1.f - w0;
        atomicAdd(&g_cnt[i0], 1);
        atomicAdd(&g_cnt[i1], 1);
    }
}

// ---------------- stage 2: padded offsets, tile->expert map, slot init ----------------
__global__ void k_setup() {
    __shared__ int soff[NE + 1];
    const int tid = threadIdx.x;
    if (tid == 0) {
        int o = 0;
        for (int e = 0; e < NE; e++) {
            soff[e] = o; g_off[e] = o; g_cursor[e] = 0;
            o += ((g_cnt[e] + BM - 1) / BM) * BM;   // pad each segment to BM
        }
        soff[NE] = o; g_off[NE] = o;
    }
    __syncthreads();
    const int ntiles = soff[NE] / BM;
    for (int i = tid; i < MAX_TILES; i += blockDim.x) {
        int ex = -1;
        if (i < ntiles) {
            int r = i * BM;
            for (int e = 0; e < NE; e++)
                if (r >= soff[e] && r < soff[e + 1]) ex = e;
        }
        g_tile_expert[i] = ex;
    }
    for (int i = tid; i < MAX_SLOTS; i += blockDim.x) {
        g_slot_token[i]  = -1;
        g_slot_weight[i] = 0.f;
    }
}

// ---------------- stage 3: scatter (token,k) -> expert slot lists ----------------
__global__ void k_scatter() {
    int i = blockIdx.x * blockDim.x + threadIdx.x;
    if (i >= NSLOT) return;
    int e   = g_tok_expert[i];
    int pos = atomicAdd(&g_cursor[e], 1);
    int s   = g_off[e] + pos;
    g_slot_token[s]  = i >> 1;          // token id
    g_slot_weight[s] = g_tok_weight[i];
}

// ---------------- stage 4: hh = silu(X W1^T) * (X W3^T), grouped per expert ----------------
__global__ __launch_bounds__(256, 2)
void k_gemm1(const float* __restrict__ x, const float* __restrict__ w1,
             const float* __restrict__ w3) {
    const int e = g_tile_expert[blockIdx.y];
    if (e < 0) return;
    const int r0  = blockIdx.y * BM;
    const int f0  = blockIdx.x * BN;
    const int tid = threadIdx.x;

    __shared__ float Xs[BK][BM];
    __shared__ float W1s[BK][BN];
    __shared__ float W3s[BK][BN];
    __shared__ int   toks[BM];

    if (tid < BM) toks[tid] = g_slot_token[r0 + tid];
    __syncthreads();

    // loader mapping: 64 rows x 32 floats per tile = 512 float4; 2 per thread
    const int row0 = tid >> 3;            // 0..31
    const int row1 = row0 + 32;           // 32..63
    const int kq0  = (tid & 7) * 4;       // 0..28

    const int t0 = toks[row0];
    const int t1 = toks[row1];
    const float* x0  = x + (size_t)(t0 >= 0 ? t0 : 0) * NH + kq0;
    const float* x1  = x + (size_t)(t1 >= 0 ? t1 : 0) * NH + kq0;
    const float* w1a = w1 + ((size_t)e * NF + f0 + row0) * NH + kq0;
    const float* w1b = w1 + ((size_t)e * NF + f0 + row1) * NH + kq0;
    const float* w3a = w3 + ((size_t)e * NF + f0 + row0) * NH + kq0;
    const float* w3b = w3 + ((size_t)e * NF + f0 + row1) * NH + kq0;

    unsigned long long acc1[4][2] = {};
    unsigned long long acc3[4][2] = {};
    const int ty = tid >> 4, tx = tid & 15;

    for (int k0 = 0; k0 < NH; k0 += BK) {
        float4 xv0 = (t0 >= 0) ? *(const float4*)x0 : make_float4(0.f, 0.f, 0.f, 0.f);
        float4 xv1 = (t1 >= 0) ? *(const float4*)x1 : make_float4(0.f, 0.f, 0.f, 0.f);
        float4 u0 = *(const float4*)w1a;
        float4 u1 = *(const float4*)w1b;
        float4 v0 = *(const float4*)w3a;
        float4 v1 = *(const float4*)w3b;
        __syncthreads();
        Xs[kq0 + 0][row0] = xv0.x; Xs[kq0 + 1][row0] = xv0.y;
        Xs[kq0 + 2][row0] = xv0.z; Xs[kq0 + 3][row0] = xv0.w;
        Xs[kq0 + 0][row1] = xv1.x; Xs[kq0 + 1][row1] = xv1.y;
        Xs[kq0 + 2][row1] = xv1.z; Xs[kq0 + 3][row1] = xv1.w;
        W1s[kq0 + 0][row0] = u0.x; W1s[kq0 + 1][row0] = u0.y;
        W1s[kq0 + 2][row0] = u0.z; W1s[kq0 + 3][row0] = u0.w;
        W1s[kq0 + 0][row1] = u1.x; W1s[kq0 + 1][row1] = u1.y;
        W1s[kq0 + 2][row1] = u1.z; W1s[kq0 + 3][row1] = u1.w;
        W3s[kq0 + 0][row0] = v0.x; W3s[kq0 + 1][row0] = v0.y;
        W3s[kq0 + 2][row0] = v0.z; W3s[kq0 + 3][row0] = v0.w;
        W3s[kq0 + 0][row1] = v1.x; W3s[kq0 + 1][row1] = v1.y;
        W3s[kq0 + 2][row1] = v1.z; W3s[kq0 + 3][row1] = v1.w;
        __syncthreads();
        x0 += BK; x1 += BK; w1a += BK; w1b += BK; w3a += BK; w3b += BK;

#pragma unroll
        for (int kk = 0; kk < BK; kk++) {
            float4 av = *(const float4*)&Xs[kk][ty * 4];
            unsigned long long p0 = pack2(av.x), p1 = pack2(av.y);
            unsigned long long p2 = pack2(av.z), p3 = pack2(av.w);
            ulonglong2 b1 = *(const ulonglong2*)&W1s[kk][tx * 4];
            ulonglong2 b3 = *(const ulonglong2*)&W3s[kk][tx * 4];
            fma2(acc1[0][0], p0, b1.x); fma2(acc1[0][1], p0, b1.y);
            fma2(acc1[1][0], p1, b1.x); fma2(acc1[1][1], p1, b1.y);
            fma2(acc1[2][0], p2, b1.x); fma2(acc1[2][1], p2, b1.y);
            fma2(acc1[3][0], p3, b1.x); fma2(acc1[3][1], p3, b1.y);
            fma2(acc3[0][0], p0, b3.x); fma2(acc3[0][1], p0, b3.y);
            fma2(acc3[1][0], p1, b3.x); fma2(acc3[1][1], p1, b3.y);
            fma2(acc3[2][0], p2, b3.x); fma2(acc3[2][1], p2, b3.y);
            fma2(acc3[3][0], p3, b3.x); fma2(acc3[3][1], p3, b3.y);
        }
    }

    // epilogue: SwiGLU, write hh (padded rows produce exact zeros)
#pragma unroll
    for (int i = 0; i < 4; i++) {
        const int r = r0 + ty * 4 + i;
        float* hp = g_hh + (size_t)r * NF + f0 + tx * 4;
#pragma unroll
        for (int jp = 0; jp < 2; jp++) {
            float2 a = unpack2(acc1[i][jp]);
            float2 b = unpack2(acc3[i][jp]);
            float h0 = (a.x / (1.f + expf(-a.x))) * b.x;
            float h1 = (a.y / (1.f + expf(-a.y))) * b.y;
            hp[jp * 2 + 0] = h0;
            hp[jp * 2 + 1] = h1;
        }
    }
}

// ---------------- stage 5: y = hh W2^T, weighted scatter-add to out ----------------
__global__ __launch_bounds__(256, 2)
void k_gemm2(const float* __restrict__ w2, float* __restrict__ out) {
    const int e = g_tile_expert[blockIdx.y];
    if (e < 0) return;
    const int r0  = blockIdx.y * BM;
    const int h0  = blockIdx.x * BN;
    const int tid = threadIdx.x;

    __shared__ float Hs[BK][BM];
    __shared__ float W2s[BK][BN];
    __shared__ int   toks[BM];
    __shared__ float wgts[BM];

    if (tid < BM) {
        toks[tid] = g_slot_token[r0 + tid];
        wgts[tid] = g_slot_weight[r0 + tid];
    }
    __syncthreads();

    const int row0 = tid >> 3;
    const int row1 = row0 + 32;
    const int kq0  = (tid & 7) * 4;

    const float* ha = g_hh + (size_t)(r0 + row0) * NF + kq0;
    const float* hb = g_hh + (size_t)(r0 + row1) * NF + kq0;
    const float* wa = w2 + ((size_t)e * NH + h0 + row0) * NF + kq0;
    const float* wb = w2 + ((size_t)e * NH + h0 + row1) * NF + kq0;

    unsigned long long acc[4][2] = {};
    const int ty = tid >> 4, tx = tid & 15;

    for (int k0 = 0; k0 < NF; k0 += BK) {
        float4 hv0 = *(const float4*)ha;
        float4 hv1 = *(const float4*)hb;
        float4 wv0 = *(const float4*)wa;
        float4 wv1 = *(const float4*)wb;
        __syncthreads();
        Hs[kq0 + 0][row0] = hv0.x; Hs[kq0 + 1][row0] = hv0.y;
        Hs[kq0 + 2][row0] = hv0.z; Hs[kq0 + 3][row0] = hv0.w;
        Hs[kq0 + 0][row1] = hv1.x; Hs[kq0 + 1][row1] = hv1.y;
        Hs[kq0 + 2][row1] = hv1.z; Hs[kq0 + 3][row1] = hv1.w;
        W2s[kq0 + 0][row0] = wv0.x; W2s[kq0 + 1][row0] = wv0.y;
        W2s[kq0 + 2][row0] = wv0.z; W2s[kq0 + 3][row0] = wv0.w;
        W2s[kq0 + 0][row1] = wv1.x; W2s[kq0 + 1][row1] = wv1.y;
        W2s[kq0 + 2][row1] = wv1.z; W2s[kq0 + 3][row1] = wv1.w;
        __syncthreads();
        ha += BK; hb += BK; wa += BK; wb += BK;

#pragma unroll
        for (int kk = 0; kk < BK; kk++) {
            float4 av = *(const float4*)&Hs[kk][ty * 4];
            unsigned long long p0 = pack2(av.x), p1 = pack2(av.y);
            unsigned long long p2 = pack2(av.z), p3 = pack2(av.w);
            ulonglong2 b = *(const ulonglong2*)&W2s[kk][tx * 4];
            fma2(acc[0][0], p0, b.x); fma2(acc[0][1], p0, b.y);
            fma2(acc[1][0], p1, b.x); fma2(acc[1][1], p1, b.y);
            fma2(acc[2][0], p2, b.x); fma2(acc[2][1], p2, b.y);
            fma2(acc[3][0], p3, b.x); fma2(acc[3][1], p3, b.y);
        }
    }

#pragma unroll
    for (int i = 0; i < 4; i++) {
        const int rl = ty * 4 + i;
        const int t  = toks[rl];
        if (t < 0) continue;
        const float w = wgts[rl];
        float* op = out + (size_t)t * NH + h0 + tx * 4;
#pragma unroll
        for (int jp = 0; jp < 2; jp++) {
            float2 v = unpack2(acc[i][jp]);
            atomicAdd(&op[jp * 2 + 0], w * v.x);  // exactly 2 adds/elem -> commutative
            atomicAdd(&op[jp * 2 + 1], w * v.y);  // -> bitwise deterministic
        }
    }
}

// ---------------- launch ----------------
extern "C" void kernel_launch(void* const* d_in, const int* in_sizes, int n_in,
                              void* d_out, int out_size) {
    const float* x  = (const float*)d_in[0];   // hidden_states [T,H]
    const float* gw = (const float*)d_in[1];   // gate_w        [E,H]
    const float* w1 = (const float*)d_in[2];   // w1            [E,F,H]
    const float* w2 = (const float*)d_in[3];   // w2            [E,H,F]
    const float* w3 = (const float*)d_in[4];   // w3            [E,F,H]
    float* out = (float*)d_out;

    const int n = NT * NH;
    k_zero<<<(n + 255) / 256, 256>>>(out, n);
    k_router<<<NT, 256>>>(x, gw);
    k_setup<<<1, 256>>>();
    k_scatter<<<(NSLOT + 255) / 256, 256>>>();
    k_gemm1<<<dim3(NF / BN, MAX_TILES), 256>>>(x, w1, w3);
    k_gemm2<<<dim3(NH / BN, MAX_TILES), 256>>>(w2, out);
}

// round 4
// speedup vs baseline: 4.1548x; 4.1533x over previous
#include <cuda_runtime.h>
#include <math.h>
#include <stdint.h>

// ---------------- problem constants ----------------
#define NT 4096
#define NH 2048
#define NF 8192
#define NE 8

#define BM 128
#define KB 32                           // K floats per stage (128B rows)
#define NSLOT (2*NT)                    // 8192
#define MAX_TILES (NSLOT/BM + NE)       // 72
#define MAX_SLOTS (MAX_TILES*BM)        // 9216
#define NST1 (NH/KB)                    // 64
#define NST2 (NF/KB)                    // 256

// ---------------- device scratch ----------------
__device__ int   g_cnt[NE];
__device__ int   g_cursor[NE];
__device__ int   g_off[NE+1];
__device__ int   g_tok_expert[NSLOT];
__device__ float g_tok_weight[NSLOT];
__device__ int   g_slot_token[MAX_SLOTS];
__device__ float g_slot_weight[MAX_SLOTS];
__device__ int   g_tile_expert[MAX_TILES];
__device__ float g_hh[(size_t)MAX_SLOTS * NF];   // ~302 MB

// smem offsets (bytes), both GEMMs: dyn smem = 66560
#define OFF_A   1024                    // A tile 128x32 tf32, 2 stages x 16384
#define OFF_B1  33792                   // B tile, 2 stages (8192 g1 / 16384 g2)
#define OFF_B3  50176                   // gemm1 only
#define DSMEM   66560

// ---------------- PTX helpers ----------------
__device__ __forceinline__ uint32_t s2u(const void* p) {
    uint32_t a;
    asm("{ .reg .u64 t; cvta.to.shared.u64 t, %1; cvt.u32.u64 %0, t; }" : "=r"(a) : "l"(p));
    return a;
}
__device__ __forceinline__ uint32_t tf32r(float x) {
    uint32_t r; asm("cvt.rna.tf32.f32 %0, %1;" : "=r"(r) : "f"(x)); return r;
}
__device__ __forceinline__ uint4 cvt4(float4 v) {
    return make_uint4(tf32r(v.x), tf32r(v.y), tf32r(v.z), tf32r(v.w));
}
#define LDSM4(r, a)                                                            \
    asm volatile("ldmatrix.sync.aligned.m8n8.x4.shared.b16 {%0,%1,%2,%3}, [%4];" \
        : "=r"((r)[0]), "=r"((r)[1]), "=r"((r)[2]), "=r"((r)[3]) : "r"(a))

__device__ __forceinline__ void mma8(float* d, const uint32_t* a, const uint32_t* b) {
    asm volatile(
        "mma.sync.aligned.m16n8k8.row.col.f32.tf32.tf32.f32 "
        "{%0,%1,%2,%3},{%4,%5,%6,%7},{%8,%9},{%0,%1,%2,%3};"
        : "+f"(d[0]), "+f"(d[1]), "+f"(d[2]), "+f"(d[3])
        : "r"(a[0]), "r"(a[1]), "r"(a[2]), "r"(a[3]), "r"(b[0]), "r"(b[1]));
}

// ---------------- small kernels (unchanged from R1) ----------------
__global__ void k_zero(float* __restrict__ out, int n) {
    int i = blockIdx.x * blockDim.x + threadIdx.x;
    if (i < n) out[i] = 0.f;
    if (blockIdx.x == 0 && threadIdx.x < NE) g_cnt[threadIdx.x] = 0;
}

__global__ void k_router(const float* __restrict__ x, const float* __restrict__ gw) {
    const int t = blockIdx.x, tid = threadIdx.x;
    float acc[NE];
#pragma unroll
    for (int e = 0; e < NE; e++) acc[e] = 0.f;
    const float* xr = x + (size_t)t * NH;
    for (int h = tid; h < NH; h += 256) {
        float xv = xr[h];
#pragma unroll
        for (int e = 0; e < NE; e++) acc[e] += xv * gw[e * NH + h];
    }
    __shared__ float part[NE][256];
#pragma unroll
    for (int e = 0; e < NE; e++) part[e][tid] = acc[e];
    __syncthreads();
    if (tid < NE) {
        float s = 0.f;
        for (int i = 0; i < 256; i++) s += part[tid][i];
        part[tid][0] = s;
    }
    __syncthreads();
    if (tid == 0) {
        float l[NE];
#pragma unroll
        for (int e = 0; e < NE; e++) l[e] = part[e][0];
        int i0 = 0;
#pragma unroll
        for (int e = 1; e < NE; e++) if (l[e] > l[i0]) i0 = e;
        int i1 = -1;
#pragma unroll
        for (int e = 0; e < NE; e++)
            if (e != i0 && (i1 < 0 || l[e] > l[i1])) i1 = e;
        float w0 = 1.f / (1.f + expf(l[i1] - l[i0]));
        g_tok_expert[2 * t] = i0;  g_tok_expert[2 * t + 1] = i1;
        g_tok_weight[2 * t] = w0;  g_tok_weight[2 * t + 1] = 1.f - w0;
        atomicAdd(&g_cnt[i0], 1);
        atomicAdd(&g_cnt[i1], 1);
    }
}

__global__ void k_setup() {
    __shared__ int soff[NE + 1];
    const int tid = threadIdx.x;
    if (tid == 0) {
        int o = 0;
        for (int e = 0; e < NE; e++) {
            soff[e] = o; g_off[e] = o; g_cursor[e] = 0;
            o += ((g_cnt[e] + BM - 1) / BM) * BM;
        }
        soff[NE] = o; g_off[NE] = o;
    }
    __syncthreads();
    const int ntiles = soff[NE] / BM;
    for (int i = tid; i < MAX_TILES; i += blockDim.x) {
        int ex = -1;
        if (i < ntiles) {
            int r = i * BM;
            for (int e = 0; e < NE; e++)
                if (r >= soff[e] && r < soff[e + 1]) ex = e;
        }
        g_tile_expert[i] = ex;
    }
    for (int i = tid; i < MAX_SLOTS; i += blockDim.x) {
        g_slot_token[i]  = -1;
        g_slot_weight[i] = 0.f;
    }
}

__global__ void k_scatter() {
    int i = blockIdx.x * blockDim.x + threadIdx.x;
    if (i >= NSLOT) return;
    int e = g_tok_expert[i];
    int pos = atomicAdd(&g_cursor[e], 1);
    int s = g_off[e] + pos;
    g_slot_token[s]  = i >> 1;
    g_slot_weight[s] = g_tok_weight[i];
}

// ---------------- GEMM1: hh = silu(X W1^T) * (X W3^T) ----------------
// tile: 128 slots x 64 ffn; warps 0-3 -> W1, warps 4-7 -> W3; warp tile 64x32
__global__ void __launch_bounds__(256, 1)
k_gemm1(const float* __restrict__ x, const float* __restrict__ w1,
        const float* __restrict__ w3) {
    const int e = g_tile_expert[blockIdx.y];
    if (e < 0) return;
    extern __shared__ char smem[];
    const uint32_t sb = s2u(smem);
    const int tid = threadIdx.x, lane = tid & 31, wid = tid >> 5;
    const int r0 = blockIdx.y * BM, f0 = blockIdx.x * 64;

    int* toks = (int*)smem;
    if (tid < BM) toks[tid] = g_slot_token[r0 + tid];
    __syncthreads();

    // loader precompute: A 1024 chunks (4/thr), each B 512 chunks (2/thr)
    const float* gA[4]; uint32_t stsA[4]; bool vA[4];
#pragma unroll
    for (int i = 0; i < 4; i++) {
        int i4 = tid + 256 * i, row = i4 >> 3, q = i4 & 7;
        int t = toks[row]; vA[i] = (t >= 0);
        gA[i] = x + (size_t)(t >= 0 ? t : 0) * NH + q * 4;
        stsA[i] = OFF_A + row * 128 + ((q ^ (row & 7)) << 4);
    }
    const float* gB1[2]; const float* gB3[2]; uint32_t stsB[2];
#pragma unroll
    for (int i = 0; i < 2; i++) {
        int i4 = tid + 256 * i, row = i4 >> 3, q = i4 & 7;
        gB1[i] = w1 + ((size_t)e * NF + f0 + row) * NH + q * 4;
        gB3[i] = w3 + ((size_t)e * NF + f0 + row) * NH + q * 4;
        stsB[i] = row * 128 + ((q ^ (row & 7)) << 4);
    }

    // prologue stage 0
#pragma unroll
    for (int i = 0; i < 4; i++) {
        float4 v = vA[i] ? *(const float4*)gA[i] : make_float4(0.f, 0.f, 0.f, 0.f);
        *(uint4*)(smem + stsA[i]) = cvt4(v);
    }
#pragma unroll
    for (int i = 0; i < 2; i++) {
        *(uint4*)(smem + OFF_B1 + stsB[i]) = cvt4(*(const float4*)gB1[i]);
        *(uint4*)(smem + OFF_B3 + stsB[i]) = cvt4(*(const float4*)gB3[i]);
    }
    __syncthreads();

    // fragment address precompute
    const int mat = wid >> 2, wm = (wid >> 1) & 1, wn = wid & 1;
    const uint32_t aTile = sb + OFF_A;
    const uint32_t bTile = sb + (mat ? OFF_B3 : OFF_B1);
    uint32_t mOff[4], nOff[2], swzA[4], swzB[4];
#pragma unroll
    for (int mf = 0; mf < 4; mf++) mOff[mf] = (wm * 64 + mf * 16 + (lane & 15)) * 128;
#pragma unroll
    for (int np = 0; np < 2; np++)
        nOff[np] = (wn * 32 + np * 16 + ((lane >> 4) << 3) + (lane & 7)) * 128;
#pragma unroll
    for (int ks = 0; ks < 4; ks++) {
        swzA[ks] = ((2 * ks + (lane >> 4)) ^ (lane & 7)) << 4;
        swzB[ks] = ((2 * ks + ((lane >> 3) & 1)) ^ (lane & 7)) << 4;
    }

    float acc[4][4][4] = {};
    float4 pA[4], pB1[2], pB3[2];

    for (int s = 0; s < NST1; s++) {
        const int cur = s & 1, nxt = (s + 1) & 1;
        const bool more = (s + 1 < NST1);
        if (more) {
#pragma unroll
            for (int i = 0; i < 4; i++) {
                gA[i] += KB;
                pA[i] = vA[i] ? *(const float4*)gA[i] : make_float4(0.f, 0.f, 0.f, 0.f);
            }
#pragma unroll
            for (int i = 0; i < 2; i++) {
                gB1[i] += KB; pB1[i] = *(const float4*)gB1[i];
                gB3[i] += KB; pB3[i] = *(const float4*)gB3[i];
            }
        }
        const uint32_t aB = aTile + cur * 16384;
        const uint32_t bB = bTile + cur * 8192;
#pragma unroll
        for (int ks = 0; ks < 4; ks++) {
            uint32_t a[4][4], b[2][4];
#pragma unroll
            for (int mf = 0; mf < 4; mf++) LDSM4(a[mf], aB + mOff[mf] + swzA[ks]);
#pragma unroll
            for (int np = 0; np < 2; np++) LDSM4(b[np], bB + nOff[np] + swzB[ks]);
#pragma unroll
            for (int mf = 0; mf < 4; mf++)
#pragma unroll
                for (int nf = 0; nf < 4; nf++)
                    mma8(acc[mf][nf], a[mf], &b[nf >> 1][(nf & 1) * 2]);
        }
        if (more) {
#pragma unroll
            for (int i = 0; i < 4; i++)
                *(uint4*)(smem + stsA[i] + nxt * 16384) = cvt4(pA[i]);
#pragma unroll
            for (int i = 0; i < 2; i++) {
                *(uint4*)(smem + OFF_B1 + stsB[i] + nxt * 8192) = cvt4(pB1[i]);
                *(uint4*)(smem + OFF_B3 + stsB[i] + nxt * 8192) = cvt4(pB3[i]);
            }
        }
        __syncthreads();
    }

    // epilogue: stage both acc sets in smem, fuse SwiGLU, write hh
    float* Sg = (float*)(smem + OFF_A + mat * 32768);
    const int rb = wm * 64, cb = wn * 32;
#pragma unroll
    for (int mf = 0; mf < 4; mf++)
#pragma unroll
        for (int nf = 0; nf < 4; nf++) {
            int r = rb + mf * 16 + (lane >> 2), c = cb + nf * 8 + (lane & 3) * 2;
            Sg[r * 64 + c]           = acc[mf][nf][0];
            Sg[r * 64 + c + 1]       = acc[mf][nf][1];
            Sg[(r + 8) * 64 + c]     = acc[mf][nf][2];
            Sg[(r + 8) * 64 + c + 1] = acc[mf][nf][3];
        }
    __syncthreads();
    const float4* S1 = (const float4*)(smem + OFF_A);
    const float4* S3 = (const float4*)(smem + OFF_A + 32768);
#pragma unroll
    for (int k2 = 0; k2 < 8; k2++) {
        int i4 = tid + 256 * k2;
        int row = i4 >> 4, c4 = i4 & 15;
        float4 a = S1[i4], g = S3[i4], o;
        o.x = a.x / (1.f + __expf(-a.x)) * g.x;
        o.y = a.y / (1.f + __expf(-a.y)) * g.y;
        o.z = a.z / (1.f + __expf(-a.z)) * g.z;
        o.w = a.w / (1.f + __expf(-a.w)) * g.w;
        *(float4*)(g_hh + (size_t)(r0 + row) * NF + f0 + c4 * 4) = o;
    }
}

// ---------------- GEMM2: out += w .* (hh W2^T) ----------------
// tile: 128 slots x 128 hidden; 8 warps 2m x 4n; warp tile 64x32
__global__ void __launch_bounds__(256, 1)
k_gemm2(const float* __restrict__ w2, float* __restrict__ out) {
    const int e = g_tile_expert[blockIdx.y];
    if (e < 0) return;
    extern __shared__ char smem[];
    const uint32_t sb = s2u(smem);
    const int tid = threadIdx.x, lane = tid & 31, wid = tid >> 5;
    const int r0 = blockIdx.y * BM, h0 = blockIdx.x * 128;

    int*   toks = (int*)smem;
    float* wgts = (float*)(smem + 512);
    if (tid < BM) {
        toks[tid] = g_slot_token[r0 + tid];
        wgts[tid] = g_slot_weight[r0 + tid];
    }

    const float* gA[4]; const float* gB[4]; uint32_t stsA[4], stsB[4];
#pragma unroll
    for (int i = 0; i < 4; i++) {
        int i4 = tid + 256 * i, row = i4 >> 3, q = i4 & 7;
        gA[i] = g_hh + (size_t)(r0 + row) * NF + q * 4;
        gB[i] = w2 + ((size_t)e * NH + h0 + row) * NF + q * 4;
        uint32_t sw = row * 128 + ((q ^ (row & 7)) << 4);
        stsA[i] = OFF_A + sw;
        stsB[i] = OFF_B1 + sw;
    }

    // prologue stage 0
#pragma unroll
    for (int i = 0; i < 4; i++) {
        *(uint4*)(smem + stsA[i]) = cvt4(*(const float4*)gA[i]);
        *(uint4*)(smem + stsB[i]) = cvt4(*(const float4*)gB[i]);
    }
    __syncthreads();

    const int wm = wid >> 2, wn = wid & 3;
    uint32_t mOff[4], nOff[2], swzA[4], swzB[4];
#pragma unroll
    for (int mf = 0; mf < 4; mf++) mOff[mf] = (wm * 64 + mf * 16 + (lane & 15)) * 128;
#pragma unroll
    for (int np = 0; np < 2; np++)
        nOff[np] = (wn * 32 + np * 16 + ((lane >> 4) << 3) + (lane & 7)) * 128;
#pragma unroll
    for (int ks = 0; ks < 4; ks++) {
        swzA[ks] = ((2 * ks + (lane >> 4)) ^ (lane & 7)) << 4;
        swzB[ks] = ((2 * ks + ((lane >> 3) & 1)) ^ (lane & 7)) << 4;
    }

    float acc[4][4][4] = {};
    float4 pA[4], pB[4];

    for (int s = 0; s < NST2; s++) {
        const int cur = s & 1, nxt = (s + 1) & 1;
        const bool more = (s + 1 < NST2);
        if (more) {
#pragma unroll
            for (int i = 0; i < 4; i++) {
                gA[i] += KB; pA[i] = *(const float4*)gA[i];
                gB[i] += KB; pB[i] = *(const float4*)gB[i];
            }
        }
        const uint32_t aB = sb + OFF_A + cur * 16384;
        const uint32_t bB = sb + OFF_B1 + cur * 16384;
#pragma unroll
        for (int ks = 0; ks < 4; ks++) {
            uint32_t a[4][4], b[2][4];
#pragma unroll
            for (int mf = 0; mf < 4; mf++) LDSM4(a[mf], aB + mOff[mf] + swzA[ks]);
#pragma unroll
            for (int np = 0; np < 2; np++) LDSM4(b[np], bB + nOff[np] + swzB[ks]);
#pragma unroll
            for (int mf = 0; mf < 4; mf++)
#pragma unroll
                for (int nf = 0; nf < 4; nf++)
                    mma8(acc[mf][nf], a[mf], &b[nf >> 1][(nf & 1) * 2]);
        }
        if (more) {
#pragma unroll
            for (int i = 0; i < 4; i++) {
                *(uint4*)(smem + stsA[i] + nxt * 16384) = cvt4(pA[i]);
                *(uint4*)(smem + stsB[i] + nxt * 16384) = cvt4(pB[i]);
            }
        }
        __syncthreads();
    }

    // epilogue: weighted scatter-add (exactly 2 adds/elem -> deterministic)
    const int rb = wm * 64, cb = wn * 32;
#pragma unroll
    for (int mf = 0; mf < 4; mf++)
#pragma unroll
        for (int nf = 0; nf < 4; nf++) {
            int r = rb + mf * 16 + (lane >> 2), c = cb + nf * 8 + (lane & 3) * 2;
            int t0 = toks[r];
            if (t0 >= 0) {
                float w = wgts[r];
                float* op = out + (size_t)t0 * NH + h0 + c;
                atomicAdd(op,     w * acc[mf][nf][0]);
                atomicAdd(op + 1, w * acc[mf][nf][1]);
            }
            int t1 = toks[r + 8];
            if (t1 >= 0) {
                float w = wgts[r + 8];
                float* op = out + (size_t)t1 * NH + h0 + c;
                atomicAdd(op,     w * acc[mf][nf][2]);
                atomicAdd(op + 1, w * acc[mf][nf][3]);
            }
        }
}

// ---------------- launch ----------------
extern "C" void kernel_launch(void* const* d_in, const int* in_sizes, int n_in,
                              void* d_out, int out_size) {
    const float* x  = (const float*)d_in[0];
    const float* gw = (const float*)d_in[1];
    const float* w1 = (const float*)d_in[2];
    const float* w2 = (const float*)d_in[3];
    const float* w3 = (const float*)d_in[4];
    float* out = (float*)d_out;

    static int configured = 0;
    if (!configured) {
        cudaFuncSetAttribute(k_gemm1, cudaFuncAttributeMaxDynamicSharedMemorySize, DSMEM);
        cudaFuncSetAttribute(k_gemm2, cudaFuncAttributeMaxDynamicSharedMemorySize, DSMEM);
        configured = 1;
    }

    const int n = NT * NH;
    k_zero<<<(n + 255) / 256, 256>>>(out, n);
    k_router<<<NT, 256>>>(x, gw);
    k_setup<<<1, 256>>>();
    k_scatter<<<(NSLOT + 255) / 256, 256>>>();
    k_gemm1<<<dim3(NF / 64, MAX_TILES), 256, DSMEM>>>(x, w1, w3);
    k_gemm2<<<dim3(NH / 128, MAX_TILES), 256, DSMEM>>>(w2, out);
}

// round 5
// speedup vs baseline: 5.4847x; 1.3201x over previous
#include <cuda_runtime.h>
#include <math.h>
#include <stdint.h>

// ---------------- problem constants ----------------
#define NT 4096
#define NH 2048
#define NF 8192
#define NE 8

#define BM 128
#define KB 32                           // K floats per stage (128B rows)
#define NSLOT (2*NT)                    // 8192
#define MAX_TILES (NSLOT/BM + NE)       // 72
#define MAX_SLOTS (MAX_TILES*BM)        // 9216
#define NST1 (NH/KB)                    // 64
#define NST2 (NF/KB)                    // 256

// smem tile layout (dynamic): toks/wgts in [0,1024), stages from 1024
#define TILE0   1024
#define SA      16384                   // A tile 128x32 f32
#define SB      16384                   // B tile 128x32 f32 (GEMM2: 2x -> 32768)
#define STRIDE  49152                   // stage stride (A + 2*B) = 48KB
#define DSMEM   (TILE0 + 4*STRIDE)     // 197632

// ---------------- device scratch ----------------
__device__ int   g_cnt[NE];
__device__ int   g_cursor[NE];
__device__ int   g_off[NE+1];
__device__ int   g_tok_expert[NSLOT];
__device__ float g_tok_weight[NSLOT];
__device__ int   g_slot_token[MAX_SLOTS];
__device__ float g_slot_weight[MAX_SLOTS];
__device__ int   g_tile_expert[MAX_TILES];
__device__ float g_hh[(size_t)MAX_SLOTS * NF];   // ~302 MB, tf32-rounded values

// ---------------- PTX helpers ----------------
__device__ __forceinline__ uint32_t s2u(const void* p) {
    uint32_t a;
    asm("{ .reg .u64 t; cvta.to.shared.u64 t, %1; cvt.u32.u64 %0, t; }" : "=r"(a) : "l"(p));
    return a;
}
__device__ __forceinline__ uint32_t tf32r(float x) {
    uint32_t r; asm("cvt.rna.tf32.f32 %0, %1;" : "=r"(r) : "f"(x)); return r;
}
__device__ __forceinline__ void cvt_frag4(uint32_t* f) {
#pragma unroll
    for (int i = 0; i < 4; i++) f[i] = tf32r(__uint_as_float(f[i]));
}
#define CP16(dst, src, sz)                                                     \
    asm volatile("cp.async.cg.shared.global [%0], [%1], 16, %2;"               \
                 :: "r"(dst), "l"(src), "r"(sz))
#define CP_COMMIT() asm volatile("cp.async.commit_group;" ::: "memory")
#define CP_WAIT2()  asm volatile("cp.async.wait_group 2;" ::: "memory")
#define CP_WAIT0()  asm volatile("cp.async.wait_group 0;" ::: "memory")

#define LDSM4(r, a)                                                            \
    asm volatile("ldmatrix.sync.aligned.m8n8.x4.shared.b16 {%0,%1,%2,%3}, [%4];" \
        : "=r"((r)[0]), "=r"((r)[1]), "=r"((r)[2]), "=r"((r)[3]) : "r"(a))

__device__ __forceinline__ void mma8(float* d, const uint32_t* a, const uint32_t* b) {
    asm volatile(
        "mma.sync.aligned.m16n8k8.row.col.f32.tf32.tf32.f32 "
        "{%0,%1,%2,%3},{%4,%5,%6,%7},{%8,%9},{%0,%1,%2,%3};"
        : "+f"(d[0]), "+f"(d[1]), "+f"(d[2]), "+f"(d[3])
        : "r"(a[0]), "r"(a[1]), "r"(a[2]), "r"(a[3]), "r"(b[0]), "r"(b[1]));
}

// ---------------- small kernels ----------------
__global__ void k_zero(float* __restrict__ out, int n) {
    int i = blockIdx.x * blockDim.x + threadIdx.x;
    if (i < n) out[i] = 0.f;
    if (blockIdx.x == 0 && threadIdx.x < NE) g_cnt[threadIdx.x] = 0;
}

__global__ void k_router(const float* __restrict__ x, const float* __restrict__ gw) {
    const int t = blockIdx.x, tid = threadIdx.x;
    float acc[NE];
#pragma unroll
    for (int e = 0; e < NE; e++) acc[e] = 0.f;
    const float* xr = x + (size_t)t * NH;
    for (int h = tid; h < NH; h += 256) {
        float xv = xr[h];
#pragma unroll
        for (int e = 0; e < NE; e++) acc[e] += xv * gw[e * NH + h];
    }
    __shared__ float part[NE][256];
#pragma unroll
    for (int e = 0; e < NE; e++) part[e][tid] = acc[e];
    __syncthreads();
    if (tid < NE) {
        float s = 0.f;
        for (int i = 0; i < 256; i++) s += part[tid][i];
        part[tid][0] = s;
    }
    __syncthreads();
    if (tid == 0) {
        float l[NE];
#pragma unroll
        for (int e = 0; e < NE; e++) l[e] = part[e][0];
        int i0 = 0;
#pragma unroll
        for (int e = 1; e < NE; e++) if (l[e] > l[i0]) i0 = e;
        int i1 = -1;
#pragma unroll
        for (int e = 0; e < NE; e++)
            if (e != i0 && (i1 < 0 || l[e] > l[i1])) i1 = e;
        float w0 = 1.f / (1.f + expf(l[i1] - l[i0]));
        g_tok_expert[2 * t] = i0;  g_tok_expert[2 * t + 1] = i1;
        g_tok_weight[2 * t] = w0;  g_tok_weight[2 * t + 1] = 1.f - w0;
        atomicAdd(&g_cnt[i0], 1);
        atomicAdd(&g_cnt[i1], 1);
    }
}

__global__ void k_setup() {
    __shared__ int soff[NE + 1];
    const int tid = threadIdx.x;
    if (tid == 0) {
        int o = 0;
        for (int e = 0; e < NE; e++) {
            soff[e] = o; g_off[e] = o; g_cursor[e] = 0;
            o += ((g_cnt[e] + BM - 1) / BM) * BM;
        }
        soff[NE] = o; g_off[NE] = o;
    }
    __syncthreads();
    const int ntiles = soff[NE] / BM;
    for (int i = tid; i < MAX_TILES; i += blockDim.x) {
        int ex = -1;
        if (i < ntiles) {
            int r = i * BM;
            for (int e = 0; e < NE; e++)
                if (r >= soff[e] && r < soff[e + 1]) ex = e;
        }
        g_tile_expert[i] = ex;
    }
    for (int i = tid; i < MAX_SLOTS; i += blockDim.x) {
        g_slot_token[i]  = -1;
        g_slot_weight[i] = 0.f;
    }
}

__global__ void k_scatter() {
    int i = blockIdx.x * blockDim.x + threadIdx.x;
    if (i >= NSLOT) return;
    int e = g_tok_expert[i];
    int pos = atomicAdd(&g_cursor[e], 1);
    int s = g_off[e] + pos;
    g_slot_token[s]  = i >> 1;
    g_slot_weight[s] = g_tok_weight[i];
}

// ---------------- GEMM1: hh = silu(X W1^T) * (X W3^T) ----------------
// tile 128 slots x 128 F; warps 0-3 -> W1, 4-7 -> W3, warp tile 64x64
__global__ void __launch_bounds__(256, 1)
k_gemm1(const float* __restrict__ x, const float* __restrict__ w1,
        const float* __restrict__ w3) {
    const int e = g_tile_expert[blockIdx.y];
    if (e < 0) return;
    extern __shared__ char smem[];
    const uint32_t sb = s2u(smem);
    const int tid = threadIdx.x, lane = tid & 31, wid = tid >> 5;
    const int r0 = blockIdx.y * BM, f0 = blockIdx.x * 128;

    int* toks = (int*)smem;
    if (tid < BM) toks[tid] = g_slot_token[r0 + tid];
    __syncthreads();

    // per-thread cp.async source/dest precompute (4 A chunks, 4 per B mat)
    const float* srcA[4]; uint32_t dstA[4], szA[4];
    const float* srcB1[4]; const float* srcB3[4]; uint32_t dstB[4];
#pragma unroll
    for (int i = 0; i < 4; i++) {
        int idx = tid + 256 * i, row = idx >> 3, q = idx & 7;
        int t = toks[row];
        szA[i]  = (t >= 0) ? 16u : 0u;
        srcA[i] = x + (size_t)(t >= 0 ? t : 0) * NH + q * 4;
        uint32_t sw = row * 128 + ((q ^ (row & 7)) << 4);
        dstA[i] = sb + TILE0 + sw;
        srcB1[i] = w1 + ((size_t)e * NF + f0 + row) * NH + q * 4;
        srcB3[i] = w3 + ((size_t)e * NF + f0 + row) * NH + q * 4;
        dstB[i]  = sb + TILE0 + SA + sw;
    }

#define G1_ISSUE(S) do {                                                       \
        uint32_t _o = ((S) & 3) * STRIDE; int _k = (S) * KB;                   \
        _Pragma("unroll") for (int i = 0; i < 4; i++)                          \
            CP16(dstA[i] + _o, srcA[i] + _k, szA[i]);                          \
        _Pragma("unroll") for (int i = 0; i < 4; i++)                          \
            CP16(dstB[i] + _o, srcB1[i] + _k, 16u);                            \
        _Pragma("unroll") for (int i = 0; i < 4; i++)                          \
            CP16(dstB[i] + _o + SB, srcB3[i] + _k, 16u);                       \
        CP_COMMIT();                                                           \
    } while (0)

    G1_ISSUE(0); G1_ISSUE(1); G1_ISSUE(2);

    // fragment addressing
    const int mat = wid >> 2, wm = (wid >> 1) & 1, wn = wid & 1;
    uint32_t mOff[4], nOff[4], swzA[4], swzB[4];
#pragma unroll
    for (int mf = 0; mf < 4; mf++) mOff[mf] = (wm * 64 + mf * 16 + (lane & 15)) * 128;
#pragma unroll
    for (int np = 0; np < 4; np++)
        nOff[np] = (wn * 64 + np * 16 + ((lane >> 4) << 3) + (lane & 7)) * 128;
#pragma unroll
    for (int ks = 0; ks < 4; ks++) {
        swzA[ks] = ((2 * ks + (lane >> 4)) ^ (lane & 7)) << 4;
        swzB[ks] = ((2 * ks + ((lane >> 3) & 1)) ^ (lane & 7)) << 4;
    }

    float acc[4][8][4] = {};

    for (int s = 0; s < NST1; s++) {
        CP_WAIT2();
        __syncthreads();
        if (s + 3 < NST1) G1_ISSUE(s + 3);
        const uint32_t aB = sb + TILE0 + (s & 3) * STRIDE;
        const uint32_t bB = aB + SA + mat * SB;
#pragma unroll
        for (int ks = 0; ks < 4; ks++) {
            uint32_t a[4][4], b[4][4];
#pragma unroll
            for (int mf = 0; mf < 4; mf++) {
                LDSM4(a[mf], aB + mOff[mf] + swzA[ks]);
                cvt_frag4(a[mf]);
            }
#pragma unroll
            for (int np = 0; np < 4; np++) {
                LDSM4(b[np], bB + nOff[np] + swzB[ks]);
                cvt_frag4(b[np]);
            }
#pragma unroll
            for (int mf = 0; mf < 4; mf++)
#pragma unroll
                for (int nf = 0; nf < 8; nf++)
                    mma8(acc[mf][nf], a[mf], &b[nf >> 1][(nf & 1) * 2]);
        }
        __syncthreads();
    }
    CP_WAIT0();
    __syncthreads();

    // epilogue: both mats -> smem planes, SwiGLU fuse, rounded store to hh
    float* Sg = (float*)(smem + TILE0 + mat * 65536);
    const int rb = wm * 64, cb = wn * 64;
#pragma unroll
    for (int mf = 0; mf < 4; mf++)
#pragma unroll
        for (int nf = 0; nf < 8; nf++) {
            int r = rb + mf * 16 + (lane >> 2), c = cb + nf * 8 + (lane & 3) * 2;
            Sg[r * 128 + c]             = acc[mf][nf][0];
            Sg[r * 128 + c + 1]         = acc[mf][nf][1];
            Sg[(r + 8) * 128 + c]       = acc[mf][nf][2];
            Sg[(r + 8) * 128 + c + 1]   = acc[mf][nf][3];
        }
    __syncthreads();
    const float4* S1 = (const float4*)(smem + TILE0);
    const float4* S3 = (const float4*)(smem + TILE0 + 65536);
#pragma unroll
    for (int k2 = 0; k2 < 16; k2++) {
        int i4 = tid + 256 * k2;
        int row = i4 >> 5, c4 = i4 & 31;
        float4 a = S1[i4], g = S3[i4];
        uint4 o;
        o.x = tf32r(a.x / (1.f + __expf(-a.x)) * g.x);
        o.y = tf32r(a.y / (1.f + __expf(-a.y)) * g.y);
        o.z = tf32r(a.z / (1.f + __expf(-a.z)) * g.z);
        o.w = tf32r(a.w / (1.f + __expf(-a.w)) * g.w);
        *(uint4*)(g_hh + (size_t)(r0 + row) * NF + f0 + c4 * 4) = o;
    }
#undef G1_ISSUE
}

// ---------------- GEMM2: out += w .* (hh W2^T) ----------------
// tile 128 slots x 256 H; 8 warps 2m x 4n, warp tile 64x64
__global__ void __launch_bounds__(256, 1)
k_gemm2(const float* __restrict__ w2, float* __restrict__ out) {
    const int e = g_tile_expert[blockIdx.y];
    if (e < 0) return;
    extern __shared__ char smem[];
    const uint32_t sb = s2u(smem);
    const int tid = threadIdx.x, lane = tid & 31, wid = tid >> 5;
    const int r0 = blockIdx.y * BM, h0 = blockIdx.x * 256;

    int*   toks = (int*)smem;
    float* wgts = (float*)(smem + 512);
    if (tid < BM) {
        toks[tid] = g_slot_token[r0 + tid];
        wgts[tid] = g_slot_weight[r0 + tid];
    }
    __syncthreads();

    const float* srcA[4]; uint32_t dstA[4];
    const float* srcB[8]; uint32_t dstB[8];
#pragma unroll
    for (int i = 0; i < 4; i++) {
        int idx = tid + 256 * i, row = idx >> 3, q = idx & 7;
        srcA[i] = g_hh + (size_t)(r0 + row) * NF + q * 4;
        dstA[i] = sb + TILE0 + row * 128 + ((q ^ (row & 7)) << 4);
    }
#pragma unroll
    for (int i = 0; i < 8; i++) {
        int idx = tid + 256 * i, row = idx >> 3, q = idx & 7;   // row 0..255
        srcB[i] = w2 + ((size_t)e * NH + h0 + row) * NF + q * 4;
        dstB[i] = sb + TILE0 + SA + row * 128 + ((q ^ (row & 7)) << 4);
    }

#define G2_ISSUE(S) do {                                                       \
        uint32_t _o = ((S) & 3) * STRIDE; int _k = (S) * KB;                   \
        _Pragma("unroll") for (int i = 0; i < 4; i++)                          \
            CP16(dstA[i] + _o, srcA[i] + _k, 16u);                             \
        _Pragma("unroll") for (int i = 0; i < 8; i++)                          \
            CP16(dstB[i] + _o, srcB[i] + _k, 16u);                             \
        CP_COMMIT();                                                           \
    } while (0)

    G2_ISSUE(0); G2_ISSUE(1); G2_ISSUE(2);

    const int wm = wid >> 2, wn = wid & 3;
    uint32_t mOff[4], nOff[4], swzA[4], swzB[4];
#pragma unroll
    for (int mf = 0; mf < 4; mf++) mOff[mf] = (wm * 64 + mf * 16 + (lane & 15)) * 128;
#pragma unroll
    for (int np = 0; np < 4; np++)
        nOff[np] = (wn * 64 + np * 16 + ((lane >> 4) << 3) + (lane & 7)) * 128;
#pragma unroll
    for (int ks = 0; ks < 4; ks++) {
        swzA[ks] = ((2 * ks + (lane >> 4)) ^ (lane & 7)) << 4;
        swzB[ks] = ((2 * ks + ((lane >> 3) & 1)) ^ (lane & 7)) << 4;
    }

    float acc[4][8][4] = {};

    for (int s = 0; s < NST2; s++) {
        CP_WAIT2();
        __syncthreads();
        if (s + 3 < NST2) G2_ISSUE(s + 3);
        const uint32_t aB = sb + TILE0 + (s & 3) * STRIDE;
        const uint32_t bB = aB + SA;
#pragma unroll
        for (int ks = 0; ks < 4; ks++) {
            uint32_t a[4][4], b[4][4];
#pragma unroll
            for (int mf = 0; mf < 4; mf++) LDSM4(a[mf], aB + mOff[mf] + swzA[ks]);
#pragma unroll
            for (int np = 0; np < 4; np++) {
                LDSM4(b[np], bB + nOff[np] + swzB[ks]);
                cvt_frag4(b[np]);
            }
#pragma unroll
            for (int mf = 0; mf < 4; mf++)
#pragma unroll
                for (int nf = 0; nf < 8; nf++)
                    mma8(acc[mf][nf], a[mf], &b[nf >> 1][(nf & 1) * 2]);
        }
        __syncthreads();
    }

    // epilogue: weighted scatter-add (exactly 2 adds/elem -> deterministic)
    const int rb = wm * 64, cb = wn * 64;
#pragma unroll
    for (int mf = 0; mf < 4; mf++)
#pragma unroll
        for (int nf = 0; nf < 8; nf++) {
            int r = rb + mf * 16 + (lane >> 2), c = cb + nf * 8 + (lane & 3) * 2;
            int t0 = toks[r];
            if (t0 >= 0) {
                float w = wgts[r];
                float* op = out + (size_t)t0 * NH + h0 + c;
                atomicAdd(op,     w * acc[mf][nf][0]);
                atomicAdd(op + 1, w * acc[mf][nf][1]);
            }
            int t1 = toks[r + 8];
            if (t1 >= 0) {
                float w = wgts[r + 8];
                float* op = out + (size_t)t1 * NH + h0 + c;
                atomicAdd(op,     w * acc[mf][nf][2]);
                atomicAdd(op + 1, w * acc[mf][nf][3]);
            }
        }
#undef G2_ISSUE
}

// ---------------- launch ----------------
extern "C" void kernel_launch(void* const* d_in, const int* in_sizes, int n_in,
                              void* d_out, int out_size) {
    const float* x  = (const float*)d_in[0];
    const float* gw = (const float*)d_in[1];
    const float* w1 = (const float*)d_in[2];
    const float* w2 = (const float*)d_in[3];
    const float* w3 = (const float*)d_in[4];
    float* out = (float*)d_out;

    static int configured = 0;
    if (!configured) {
        cudaFuncSetAttribute(k_gemm1, cudaFuncAttributeMaxDynamicSharedMemorySize, DSMEM);
        cudaFuncSetAttribute(k_gemm2, cudaFuncAttributeMaxDynamicSharedMemorySize, DSMEM);
        configured = 1;
    }

    const int n = NT * NH;
    k_zero<<<(n + 255) / 256, 256>>>(out, n);
    k_router<<<NT, 256>>>(x, gw);
    k_setup<<<1, 256>>>();
    k_scatter<<<(NSLOT + 255) / 256, 256>>>();
    k_gemm1<<<dim3(NF / 128, MAX_TILES), 256, DSMEM>>>(x, w1, w3);
    k_gemm2<<<dim3(NH / 256, MAX_TILES), 256, DSMEM>>>(w2, out);
}

// round 6
// speedup vs baseline: 5.7585x; 1.0499x over previous
#include <cuda_runtime.h>
#include <math.h>
#include <stdint.h>

// ---------------- problem constants ----------------
#define NT 4096
#define NH 2048
#define NF 8192
#define NE 8

#define BM 128
#define KB 32                           // K floats per stage (128B rows)
#define NSLOT (2*NT)                    // 8192
#define MAX_TILES (NSLOT/BM + NE)       // 72
#define MAX_SLOTS (MAX_TILES*BM)        // 9216
#define NST1 (NH/KB)                    // 64
#define NST2 (NF/KB)                    // 256

// smem tile layout (dynamic): toks/wgts in [0,1024), stages from 1024
#define TILE0   1024
#define SA      16384                   // A tile 128x32 f32
#define SB      16384                   // B tile 128x32 f32
#define STRIDE  49152                   // stage stride (A + 2*B) = 48KB
#define DSMEM   (TILE0 + 4*STRIDE)      // 197632

// ---------------- device scratch ----------------
__device__ int   g_cnt[NE];
__device__ int   g_cursor[NE];
__device__ int   g_off[NE+1];
__device__ int   g_tok_expert[NSLOT];
__device__ float g_tok_weight[NSLOT];
__device__ int   g_slot_token[MAX_SLOTS];
__device__ float g_slot_weight[MAX_SLOTS];
__device__ int   g_tile_expert[MAX_TILES];
__device__ float g_hh[(size_t)MAX_SLOTS * NF];   // ~302 MB, tf32-rounded
__device__ float g_xr[(size_t)NT * NH];          // 33 MB, tf32-rounded x

// ---------------- PTX helpers ----------------
__device__ __forceinline__ uint32_t s2u(const void* p) {
    uint32_t a;
    asm("{ .reg .u64 t; cvta.to.shared.u64 t, %1; cvt.u32.u64 %0, t; }" : "=r"(a) : "l"(p));
    return a;
}
__device__ __forceinline__ uint32_t tf32r(float x) {
    uint32_t r; asm("cvt.rna.tf32.f32 %0, %1;" : "=r"(r) : "f"(x)); return r;
}
__device__ __forceinline__ void cvt_frag4(uint32_t* f) {
#pragma unroll
    for (int i = 0; i < 4; i++) f[i] = tf32r(__uint_as_float(f[i]));
}
#define CP16(dst, src, sz)                                                     \
    asm volatile("cp.async.cg.shared.global [%0], [%1], 16, %2;"               \
                 :: "r"(dst), "l"(src), "r"(sz))
#define CP_COMMIT() asm volatile("cp.async.commit_group;" ::: "memory")
#define CP_WAIT2()  asm volatile("cp.async.wait_group 2;" ::: "memory")
#define CP_WAIT0()  asm volatile("cp.async.wait_group 0;" ::: "memory")

#define LDSM4(r, a)                                                            \
    asm volatile("ldmatrix.sync.aligned.m8n8.x4.shared.b16 {%0,%1,%2,%3}, [%4];" \
        : "=r"((r)[0]), "=r"((r)[1]), "=r"((r)[2]), "=r"((r)[3]) : "r"(a))

__device__ __forceinline__ void mma8(float* d, const uint32_t* a, const uint32_t* b) {
    asm volatile(
        "mma.sync.aligned.m16n8k8.row.col.f32.tf32.tf32.f32 "
        "{%0,%1,%2,%3},{%4,%5,%6,%7},{%8,%9},{%0,%1,%2,%3};"
        : "+f"(d[0]), "+f"(d[1]), "+f"(d[2]), "+f"(d[3])
        : "r"(a[0]), "r"(a[1]), "r"(a[2]), "r"(a[3]), "r"(b[0]), "r"(b[1]));
}

// ---------------- small kernels ----------------
__global__ void k_zero(float* __restrict__ out, int n) {
    int i = blockIdx.x * blockDim.x + threadIdx.x;
    if (i < n) out[i] = 0.f;
    if (blockIdx.x == 0 && threadIdx.x < NE) g_cnt[threadIdx.x] = 0;
}

// pre-round hidden_states to tf32 (33MB, ~15us)
__global__ void k_roundx(const float* __restrict__ x) {
    int i = blockIdx.x * blockDim.x + threadIdx.x;
    float4 v = *((const float4*)x + i);
    uint4 u = make_uint4(tf32r(v.x), tf32r(v.y), tf32r(v.z), tf32r(v.w));
    *((uint4*)g_xr + i) = u;
}

__global__ void k_router(const float* __restrict__ x, const float* __restrict__ gw) {
    const int t = blockIdx.x, tid = threadIdx.x;
    float acc[NE];
#pragma unroll
    for (int e = 0; e < NE; e++) acc[e] = 0.f;
    const float* xr = x + (size_t)t * NH;
    for (int h = tid; h < NH; h += 256) {
        float xv = xr[h];
#pragma unroll
        for (int e = 0; e < NE; e++) acc[e] += xv * gw[e * NH + h];
    }
    __shared__ float part[NE][256];
#pragma unroll
    for (int e = 0; e < NE; e++) part[e][tid] = acc[e];
    __syncthreads();
    if (tid < NE) {
        float s = 0.f;
        for (int i = 0; i < 256; i++) s += part[tid][i];
        part[tid][0] = s;
    }
    __syncthreads();
    if (tid == 0) {
        float l[NE];
#pragma unroll
        for (int e = 0; e < NE; e++) l[e] = part[e][0];
        int i0 = 0;
#pragma unroll
        for (int e = 1; e < NE; e++) if (l[e] > l[i0]) i0 = e;
        int i1 = -1;
#pragma unroll
        for (int e = 0; e < NE; e++)
            if (e != i0 && (i1 < 0 || l[e] > l[i1])) i1 = e;
        float w0 = 1.f / (1.f + expf(l[i1] - l[i0]));
        g_tok_expert[2 * t] = i0;  g_tok_expert[2 * t + 1] = i1;
        g_tok_weight[2 * t] = w0;  g_tok_weight[2 * t + 1] = 1.f - w0;
        atomicAdd(&g_cnt[i0], 1);
        atomicAdd(&g_cnt[i1], 1);
    }
}

__global__ void k_setup() {
    __shared__ int soff[NE + 1];
    const int tid = threadIdx.x;
    if (tid == 0) {
        int o = 0;
        for (int e = 0; e < NE; e++) {
            soff[e] = o; g_off[e] = o; g_cursor[e] = 0;
            o += ((g_cnt[e] + BM - 1) / BM) * BM;
        }
        soff[NE] = o; g_off[NE] = o;
    }
    __syncthreads();
    const int ntiles = soff[NE] / BM;
    for (int i = tid; i < MAX_TILES; i += blockDim.x) {
        int ex = -1;
        if (i < ntiles) {
            int r = i * BM;
            for (int e = 0; e < NE; e++)
                if (r >= soff[e] && r < soff[e + 1]) ex = e;
        }
        g_tile_expert[i] = ex;
    }
    for (int i = tid; i < MAX_SLOTS; i += blockDim.x) {
        g_slot_token[i]  = -1;
        g_slot_weight[i] = 0.f;
    }
}

__global__ void k_scatter() {
    int i = blockIdx.x * blockDim.x + threadIdx.x;
    if (i >= NSLOT) return;
    int e = g_tok_expert[i];
    int pos = atomicAdd(&g_cursor[e], 1);
    int s = g_off[e] + pos;
    g_slot_token[s]  = i >> 1;
    g_slot_weight[s] = g_tok_weight[i];
}

// ---------------- GEMM1: hh = silu(X W1^T) * (X W3^T) ----------------
// grid (x=tiles, y=F blocks); tile 128 slots x 128 F per mat, warp tile 64x64
__global__ void __launch_bounds__(256, 1)
k_gemm1(const float* __restrict__ w1, const float* __restrict__ w3) {
    const int e = g_tile_expert[blockIdx.x];
    if (e < 0) return;
    extern __shared__ char smem[];
    const uint32_t sb = s2u(smem);
    const int tid = threadIdx.x, lane = tid & 31, wid = tid >> 5;
    const int r0 = blockIdx.x * BM, f0 = blockIdx.y * 128;

    int* toks = (int*)smem;
    if (tid < BM) toks[tid] = g_slot_token[r0 + tid];
    __syncthreads();

    const float* srcA[4]; uint32_t dstA[4], szA[4];
    const float* srcB1[4]; const float* srcB3[4]; uint32_t dstB[4];
#pragma unroll
    for (int i = 0; i < 4; i++) {
        int idx = tid + 256 * i, row = idx >> 3, q = idx & 7;
        int t = toks[row];
        szA[i]  = (t >= 0) ? 16u : 0u;
        srcA[i] = g_xr + (size_t)(t >= 0 ? t : 0) * NH + q * 4;   // pre-rounded
        uint32_t sw = row * 128 + ((q ^ (row & 7)) << 4);
        dstA[i] = sb + TILE0 + sw;
        srcB1[i] = w1 + ((size_t)e * NF + f0 + row) * NH + q * 4;
        srcB3[i] = w3 + ((size_t)e * NF + f0 + row) * NH + q * 4;
        dstB[i]  = sb + TILE0 + SA + sw;
    }

#define G1_ISSUE(S) do {                                                       \
        uint32_t _o = ((S) & 3) * STRIDE; int _k = (S) * KB;                   \
        _Pragma("unroll") for (int i = 0; i < 4; i++)                          \
            CP16(dstA[i] + _o, srcA[i] + _k, szA[i]);                          \
        _Pragma("unroll") for (int i = 0; i < 4; i++)                          \
            CP16(dstB[i] + _o, srcB1[i] + _k, 16u);                            \
        _Pragma("unroll") for (int i = 0; i < 4; i++)                          \
            CP16(dstB[i] + _o + SB, srcB3[i] + _k, 16u);                       \
        CP_COMMIT();                                                           \
    } while (0)

    G1_ISSUE(0); G1_ISSUE(1); G1_ISSUE(2);

    const int mat = wid >> 2, wm = (wid >> 1) & 1, wn = wid & 1;
    uint32_t mOff[4], nOff[4], swzA[4], swzB[4];
#pragma unroll
    for (int mf = 0; mf < 4; mf++) mOff[mf] = (wm * 64 + mf * 16 + (lane & 15)) * 128;
#pragma unroll
    for (int np = 0; np < 4; np++)
        nOff[np] = (wn * 64 + np * 16 + ((lane >> 4) << 3) + (lane & 7)) * 128;
#pragma unroll
    for (int ks = 0; ks < 4; ks++) {
        swzA[ks] = ((2 * ks + (lane >> 4)) ^ (lane & 7)) << 4;
        swzB[ks] = ((2 * ks + ((lane >> 3) & 1)) ^ (lane & 7)) << 4;
    }

    float acc[4][8][4] = {};

    for (int s = 0; s < NST1; s++) {
        CP_WAIT2();
        __syncthreads();
        if (s + 3 < NST1) G1_ISSUE(s + 3);
        const uint32_t aB = sb + TILE0 + (s & 3) * STRIDE;
        const uint32_t bB = aB + SA + mat * SB;
#pragma unroll
        for (int ks = 0; ks < 4; ks++) {
            uint32_t a[4][4], b[4][4];
#pragma unroll
            for (int mf = 0; mf < 4; mf++) LDSM4(a[mf], aB + mOff[mf] + swzA[ks]);
#pragma unroll
            for (int np = 0; np < 4; np++) {
                LDSM4(b[np], bB + nOff[np] + swzB[ks]);
                cvt_frag4(b[np]);
            }
#pragma unroll
            for (int mf = 0; mf < 4; mf++)
#pragma unroll
                for (int nf = 0; nf < 8; nf++)
                    mma8(acc[mf][nf], a[mf], &b[nf >> 1][(nf & 1) * 2]);
        }
        __syncthreads();
    }
    CP_WAIT0();
    __syncthreads();

    // epilogue: both mats -> smem planes, SwiGLU fuse, rounded store to hh
    float* Sg = (float*)(smem + TILE0 + mat * 65536);
    const int rb = wm * 64, cb = wn * 64;
#pragma unroll
    for (int mf = 0; mf < 4; mf++)
#pragma unroll
        for (int nf = 0; nf < 8; nf++) {
            int r = rb + mf * 16 + (lane >> 2), c = cb + nf * 8 + (lane & 3) * 2;
            Sg[r * 128 + c]             = acc[mf][nf][0];
            Sg[r * 128 + c + 1]         = acc[mf][nf][1];
            Sg[(r + 8) * 128 + c]       = acc[mf][nf][2];
            Sg[(r + 8) * 128 + c + 1]   = acc[mf][nf][3];
        }
    __syncthreads();
    const float4* S1 = (const float4*)(smem + TILE0);
    const float4* S3 = (const float4*)(smem + TILE0 + 65536);
#pragma unroll
    for (int k2 = 0; k2 < 16; k2++) {
        int i4 = tid + 256 * k2;
        int row = i4 >> 5, c4 = i4 & 31;
        float4 a = S1[i4], g = S3[i4];
        uint4 o;
        o.x = tf32r(a.x / (1.f + __expf(-a.x)) * g.x);
        o.y = tf32r(a.y / (1.f + __expf(-a.y)) * g.y);
        o.z = tf32r(a.z / (1.f + __expf(-a.z)) * g.z);
        o.w = tf32r(a.w / (1.f + __expf(-a.w)) * g.w);
        *(uint4*)(g_hh + (size_t)(r0 + row) * NF + f0 + c4 * 4) = o;
    }
#undef G1_ISSUE
}

// ---------------- GEMM2: out += w .* (hh W2^T) ----------------
// grid (x=tiles, y=H blocks); tile 128 slots x 256 H, warp tile 64x64
__global__ void __launch_bounds__(256, 1)
k_gemm2(const float* __restrict__ w2, float* __restrict__ out) {
    const int e = g_tile_expert[blockIdx.x];
    if (e < 0) return;
    extern __shared__ char smem[];
    const uint32_t sb = s2u(smem);
    const int tid = threadIdx.x, lane = tid & 31, wid = tid >> 5;
    const int r0 = blockIdx.x * BM, h0 = blockIdx.y * 256;

    int*   toks = (int*)smem;
    float* wgts = (float*)(smem + 512);
    if (tid < BM) {
        toks[tid] = g_slot_token[r0 + tid];
        wgts[tid] = g_slot_weight[r0 + tid];
    }
    __syncthreads();

    const float* srcA[4]; uint32_t dstA[4];
    const float* srcB[8]; uint32_t dstB[8];
#pragma unroll
    for (int i = 0; i < 4; i++) {
        int idx = tid + 256 * i, row = idx >> 3, q = idx & 7;
        srcA[i] = g_hh + (size_t)(r0 + row) * NF + q * 4;
        dstA[i] = sb + TILE0 + row * 128 + ((q ^ (row & 7)) << 4);
    }
#pragma unroll
    for (int i = 0; i < 8; i++) {
        int idx = tid + 256 * i, row = idx >> 3, q = idx & 7;   // row 0..255
        srcB[i] = w2 + ((size_t)e * NH + h0 + row) * NF + q * 4;
        dstB[i] = sb + TILE0 + SA + row * 128 + ((q ^ (row & 7)) << 4);
    }

#define G2_ISSUE(S) do {                                                       \
        uint32_t _o = ((S) & 3) * STRIDE; int _k = (S) * KB;                   \
        _Pragma("unroll") for (int i = 0; i < 4; i++)                          \
            CP16(dstA[i] + _o, srcA[i] + _k, 16u);                             \
        _Pragma("unroll") for (int i = 0; i < 8; i++)                          \
            CP16(dstB[i] + _o, srcB[i] + _k, 16u);                             \
        CP_COMMIT();                                                           \
    } while (0)

    G2_ISSUE(0); G2_ISSUE(1); G2_ISSUE(2);

    const int wm = wid >> 2, wn = wid & 3;
    uint32_t mOff[4], nOff[4], swzA[4], swzB[4];
#pragma unroll
    for (int mf = 0; mf < 4; mf++) mOff[mf] = (wm * 64 + mf * 16 + (lane & 15)) * 128;
#pragma unroll
    for (int np = 0; np < 4; np++)
        nOff[np] = (wn * 64 + np * 16 + ((lane >> 4) << 3) + (lane & 7)) * 128;
#pragma unroll
    for (int ks = 0; ks < 4; ks++) {
        swzA[ks] = ((2 * ks + (lane >> 4)) ^ (lane & 7)) << 4;
        swzB[ks] = ((2 * ks + ((lane >> 3) & 1)) ^ (lane & 7)) << 4;
    }

    float acc[4][8][4] = {};

    for (int s = 0; s < NST2; s++) {
        CP_WAIT2();
        __syncthreads();
        if (s + 3 < NST2) G2_ISSUE(s + 3);
        const uint32_t aB = sb + TILE0 + (s & 3) * STRIDE;
        const uint32_t bB = aB + SA;
#pragma unroll
        for (int ks = 0; ks < 4; ks++) {
            uint32_t a[4][4], b[4][4];
#pragma unroll
            for (int mf = 0; mf < 4; mf++) LDSM4(a[mf], aB + mOff[mf] + swzA[ks]);
#pragma unroll
            for (int np = 0; np < 4; np++) {
                LDSM4(b[np], bB + nOff[np] + swzB[ks]);
                cvt_frag4(b[np]);
            }
#pragma unroll
            for (int mf = 0; mf < 4; mf++)
#pragma unroll
                for (int nf = 0; nf < 8; nf++)
                    mma8(acc[mf][nf], a[mf], &b[nf >> 1][(nf & 1) * 2]);
        }
        __syncthreads();
    }

    // epilogue: weighted scatter-add (exactly 2 adds/elem -> deterministic)
    const int rb = wm * 64, cb = wn * 64;
#pragma unroll
    for (int mf = 0; mf < 4; mf++)
#pragma unroll
        for (int nf = 0; nf < 8; nf++) {
            int r = rb + mf * 16 + (lane >> 2), c = cb + nf * 8 + (lane & 3) * 2;
            int t0 = toks[r];
            if (t0 >= 0) {
                float w = wgts[r];
                float* op = out + (size_t)t0 * NH + h0 + c;
                atomicAdd(op,     w * acc[mf][nf][0]);
                atomicAdd(op + 1, w * acc[mf][nf][1]);
            }
            int t1 = toks[r + 8];
            if (t1 >= 0) {
                float w = wgts[r + 8];
                float* op = out + (size_t)t1 * NH + h0 + c;
                atomicAdd(op,     w * acc[mf][nf][2]);
                atomicAdd(op + 1, w * acc[mf][nf][3]);
            }
        }
#undef G2_ISSUE
}

// ---------------- launch ----------------
extern "C" void kernel_launch(void* const* d_in, const int* in_sizes, int n_in,
                              void* d_out, int out_size) {
    const float* x  = (const float*)d_in[0];
    const float* gw = (const float*)d_in[1];
    const float* w1 = (const float*)d_in[2];
    const float* w2 = (const float*)d_in[3];
    const float* w3 = (const float*)d_in[4];
    float* out = (float*)d_out;

    static int configured = 0;
    if (!configured) {
        cudaFuncSetAttribute(k_gemm1, cudaFuncAttributeMaxDynamicSharedMemorySize, DSMEM);
        cudaFuncSetAttribute(k_gemm2, cudaFuncAttributeMaxDynamicSharedMemorySize, DSMEM);
        configured = 1;
    }

    const int n = NT * NH;
    k_zero<<<(n + 255) / 256, 256>>>(out, n);
    k_roundx<<<(NT * NH / 4 + 255) / 256, 256>>>(x);
    k_router<<<NT, 256>>>(x, gw);
    k_setup<<<1, 256>>>();
    k_scatter<<<(NSLOT + 255) / 256, 256>>>();
    k_gemm1<<<dim3(MAX_TILES, NF / 128), 256, DSMEM>>>(w1, w3);
    k_gemm2<<<dim3(MAX_TILES, NH / 256), 256, DSMEM>>>(w2, out);
}

// round 7
// speedup vs baseline: 9.5995x; 1.6670x over previous
#include <cuda_runtime.h>
#include <cuda_fp16.h>
#include <math.h>
#include <stdint.h>

// ---------------- problem constants ----------------
#define NT 4096
#define NH 2048
#define NF 8192
#define NE 8

#define BM 128
#define KB 64                           // K halves per stage (128B rows)
#define NSLOT (2*NT)                    // 8192
#define MAX_TILES (NSLOT/BM + NE)       // 72
#define MAX_SLOTS (MAX_TILES*BM)        // 9216
#define NST1 (NH/KB)                    // 32
#define NST2 (NF/KB)                    // 128

// smem: toks/wgts in [0,1024), stages from 1024; stage stride 48KB, 4 stages
#define TILE0   1024
#define SA      16384                   // A tile 128x64 fp16
#define STRIDE  49152
#define DSMEM   (TILE0 + 4*STRIDE)      // 197632

// ---------------- device scratch ----------------
__device__ int    g_cnt[NE];
__device__ int    g_cursor[NE];
__device__ int    g_off[NE+1];
__device__ int    g_tok_expert[NSLOT];
__device__ float  g_tok_weight[NSLOT];
__device__ int    g_slot_token[MAX_SLOTS];
__device__ float  g_slot_weight[MAX_SLOTS];
__device__ int    g_tile_expert[MAX_TILES];
__device__ __half g_hh[(size_t)MAX_SLOTS * NF];      // 151 MB
__device__ __half g_xh[(size_t)NT * NH];             // 16 MB
__device__ __half g_w1h[(size_t)NE * NF * NH];       // 268 MB
__device__ __half g_w3h[(size_t)NE * NF * NH];       // 268 MB
__device__ __half g_w2h[(size_t)NE * NH * NF];       // 268 MB

// ---------------- PTX helpers ----------------
__device__ __forceinline__ uint32_t s2u(const void* p) {
    uint32_t a;
    asm("{ .reg .u64 t; cvta.to.shared.u64 t, %1; cvt.u32.u64 %0, t; }" : "=r"(a) : "l"(p));
    return a;
}
#define CP16(dst, src, sz)                                                     \
    asm volatile("cp.async.cg.shared.global [%0], [%1], 16, %2;"               \
                 :: "r"(dst), "l"(src), "r"(sz))
#define CP_COMMIT() asm volatile("cp.async.commit_group;" ::: "memory")
#define CP_WAIT2()  asm volatile("cp.async.wait_group 2;" ::: "memory")

#define LDSM4(r, a)                                                            \
    asm volatile("ldmatrix.sync.aligned.m8n8.x4.shared.b16 {%0,%1,%2,%3}, [%4];" \
        : "=r"((r)[0]), "=r"((r)[1]), "=r"((r)[2]), "=r"((r)[3]) : "r"(a))

__device__ __forceinline__ void mma16(float* d, const uint32_t* a, const uint32_t* b) {
    asm volatile(
        "mma.sync.aligned.m16n8k16.row.col.f32.f16.f16.f32 "
        "{%0,%1,%2,%3},{%4,%5,%6,%7},{%8,%9},{%0,%1,%2,%3};"
        : "+f"(d[0]), "+f"(d[1]), "+f"(d[2]), "+f"(d[3])
        : "r"(a[0]), "r"(a[1]), "r"(a[2]), "r"(a[3]), "r"(b[0]), "r"(b[1]));
}

// ---------------- small kernels ----------------
__global__ void k_zero(float* __restrict__ out, int n) {
    int i = blockIdx.x * blockDim.x + threadIdx.x;
    if (i < n) out[i] = 0.f;
    if (blockIdx.x == 0 && threadIdx.x < NE) g_cnt[threadIdx.x] = 0;
}

// fp32 -> fp16 bulk conversion (vectorized)
__global__ void k_cvt(const float* __restrict__ src, __half* __restrict__ dst, int n4) {
    int i = blockIdx.x * blockDim.x + threadIdx.x;
    if (i >= n4) return;
    float4 v = ((const float4*)src)[i];
    __half2 lo = __floats2half2_rn(v.x, v.y);
    __half2 hi = __floats2half2_rn(v.z, v.w);
    ((__half2*)dst)[2 * i]     = lo;
    ((__half2*)dst)[2 * i + 1] = hi;
}

__global__ void k_router(const float* __restrict__ x, const float* __restrict__ gw) {
    const int t = blockIdx.x, tid = threadIdx.x;
    float acc[NE];
#pragma unroll
    for (int e = 0; e < NE; e++) acc[e] = 0.f;
    const float* xr = x + (size_t)t * NH;
    for (int h = tid; h < NH; h += 256) {
        float xv = xr[h];
#pragma unroll
        for (int e = 0; e < NE; e++) acc[e] += xv * gw[e * NH + h];
    }
    __shared__ float part[NE][256];
#pragma unroll
    for (int e = 0; e < NE; e++) part[e][tid] = acc[e];
    __syncthreads();
    if (tid < NE) {
        float s = 0.f;
        for (int i = 0; i < 256; i++) s += part[tid][i];
        part[tid][0] = s;
    }
    __syncthreads();
    if (tid == 0) {
        float l[NE];
#pragma unroll
        for (int e = 0; e < NE; e++) l[e] = part[e][0];
        int i0 = 0;
#pragma unroll
        for (int e = 1; e < NE; e++) if (l[e] > l[i0]) i0 = e;
        int i1 = -1;
#pragma unroll
        for (int e = 0; e < NE; e++)
            if (e != i0 && (i1 < 0 || l[e] > l[i1])) i1 = e;
        float w0 = 1.f / (1.f + expf(l[i1] - l[i0]));
        g_tok_expert[2 * t] = i0;  g_tok_expert[2 * t + 1] = i1;
        g_tok_weight[2 * t] = w0;  g_tok_weight[2 * t + 1] = 1.f - w0;
        atomicAdd(&g_cnt[i0], 1);
        atomicAdd(&g_cnt[i1], 1);
    }
}

__global__ void k_setup() {
    __shared__ int soff[NE + 1];
    const int tid = threadIdx.x;
    if (tid == 0) {
        int o = 0;
        for (int e = 0; e < NE; e++) {
            soff[e] = o; g_off[e] = o; g_cursor[e] = 0;
            o += ((g_cnt[e] + BM - 1) / BM) * BM;
        }
        soff[NE] = o; g_off[NE] = o;
    }
    __syncthreads();
    const int ntiles = soff[NE] / BM;
    for (int i = tid; i < MAX_TILES; i += blockDim.x) {
        int ex = -1;
        if (i < ntiles) {
            int r = i * BM;
            for (int e = 0; e < NE; e++)
                if (r >= soff[e] && r < soff[e + 1]) ex = e;
        }
        g_tile_expert[i] = ex;
    }
    for (int i = tid; i < MAX_SLOTS; i += blockDim.x) {
        g_slot_token[i]  = -1;
        g_slot_weight[i] = 0.f;
    }
}

__global__ void k_scatter() {
    int i = blockIdx.x * blockDim.x + threadIdx.x;
    if (i >= NSLOT) return;
    int e = g_tok_expert[i];
    int pos = atomicAdd(&g_cursor[e], 1);
    int s = g_off[e] + pos;
    g_slot_token[s]  = i >> 1;
    g_slot_weight[s] = g_tok_weight[i];
}

// ---------------- GEMM1: hh = silu(X W1^T) * (X W3^T), fp16 MMA ----------------
// grid (x=tiles, y=F/128); warps 0-3 -> W1, 4-7 -> W3, warp tile 64x64
__global__ void __launch_bounds__(256, 1)
k_gemm1() {
    const int e = g_tile_expert[blockIdx.x];
    if (e < 0) return;
    extern __shared__ char smem[];
    const uint32_t sb = s2u(smem);
    const int tid = threadIdx.x, lane = tid & 31, wid = tid >> 5;
    const int r0 = blockIdx.x * BM, f0 = blockIdx.y * 128;

    int* toks = (int*)smem;
    if (tid < BM) toks[tid] = g_slot_token[r0 + tid];
    __syncthreads();

    // loaders: chunks = 16B = 8 halves; rows 128B = 64 halves (K per stage)
    const __half* srcA[4]; uint32_t dstA[4], szA[4];
    const __half* srcB1[4]; const __half* srcB3[4]; uint32_t dstB[4];
#pragma unroll
    for (int i = 0; i < 4; i++) {
        int idx = tid + 256 * i, row = idx >> 3, q = idx & 7;
        int t = toks[row];
        szA[i]  = (t >= 0) ? 16u : 0u;
        srcA[i] = g_xh + (size_t)(t >= 0 ? t : 0) * NH + q * 8;
        uint32_t sw = row * 128 + ((q ^ (row & 7)) << 4);
        dstA[i] = sb + TILE0 + sw;
        srcB1[i] = g_w1h + ((size_t)e * NF + f0 + row) * NH + q * 8;
        srcB3[i] = g_w3h + ((size_t)e * NF + f0 + row) * NH + q * 8;
        dstB[i]  = sb + TILE0 + SA + sw;
    }

#define G1_ISSUE(S) do {                                                       \
        uint32_t _o = ((S) & 3) * STRIDE; int _k = (S) * KB;                   \
        _Pragma("unroll") for (int i = 0; i < 4; i++)                          \
            CP16(dstA[i] + _o, srcA[i] + _k, szA[i]);                          \
        _Pragma("unroll") for (int i = 0; i < 4; i++)                          \
            CP16(dstB[i] + _o, srcB1[i] + _k, 16u);                            \
        _Pragma("unroll") for (int i = 0; i < 4; i++)                          \
            CP16(dstB[i] + _o + SA, srcB3[i] + _k, 16u);                       \
        CP_COMMIT();                                                           \
    } while (0)

    G1_ISSUE(0); G1_ISSUE(1); G1_ISSUE(2);

    const int mat = wid >> 2, wm = (wid >> 1) & 1, wn = wid & 1;
    uint32_t mOff[4], nOff[4], swzA[4], swzB[4];
#pragma unroll
    for (int mf = 0; mf < 4; mf++) mOff[mf] = (wm * 64 + mf * 16 + (lane & 15)) * 128;
#pragma unroll
    for (int np = 0; np < 4; np++)
        nOff[np] = (wn * 64 + np * 16 + ((lane >> 4) << 3) + (lane & 7)) * 128;
#pragma unroll
    for (int ks = 0; ks < 4; ks++) {
        swzA[ks] = ((2 * ks + (lane >> 4)) ^ (lane & 7)) << 4;
        swzB[ks] = ((2 * ks + ((lane >> 3) & 1)) ^ (lane & 7)) << 4;
    }

    float acc[4][8][4] = {};

    for (int s = 0; s < NST1; s++) {
        CP_WAIT2();
        __syncthreads();
        if (s + 3 < NST1) G1_ISSUE(s + 3); else CP_COMMIT();  // keep group count exact
        const uint32_t aB = sb + TILE0 + (s & 3) * STRIDE;
        const uint32_t bB = aB + SA + mat * SA;
#pragma unroll
        for (int ks = 0; ks < 4; ks++) {                      // 4 x k16 = K64
            uint32_t a[4][4], b[4][4];
#pragma unroll
            for (int mf = 0; mf < 4; mf++) LDSM4(a[mf], aB + mOff[mf] + swzA[ks]);
#pragma unroll
            for (int np = 0; np < 4; np++) LDSM4(b[np], bB + nOff[np] + swzB[ks]);
#pragma unroll
            for (int mf = 0; mf < 4; mf++)
#pragma unroll
                for (int nf = 0; nf < 8; nf++)
                    mma16(acc[mf][nf], a[mf], &b[nf >> 1][(nf & 1) * 2]);
        }
    }
    __syncthreads();   // all MMA reads of smem done before epilogue reuse

    // epilogue: both mats -> fp32 smem planes, SwiGLU fuse, fp16 store to hh
    float* Sg = (float*)(smem + TILE0 + mat * 65536);
    const int rb = wm * 64, cb = wn * 64;
#pragma unroll
    for (int mf = 0; mf < 4; mf++)
#pragma unroll
        for (int nf = 0; nf < 8; nf++) {
            int r = rb + mf * 16 + (lane >> 2), c = cb + nf * 8 + (lane & 3) * 2;
            Sg[r * 128 + c]             = acc[mf][nf][0];
            Sg[r * 128 + c + 1]         = acc[mf][nf][1];
            Sg[(r + 8) * 128 + c]       = acc[mf][nf][2];
            Sg[(r + 8) * 128 + c + 1]   = acc[mf][nf][3];
        }
    __syncthreads();
    const float4* S1 = (const float4*)(smem + TILE0);
    const float4* S3 = (const float4*)(smem + TILE0 + 65536);
#pragma unroll
    for (int k2 = 0; k2 < 16; k2++) {
        int i4 = tid + 256 * k2;
        int row = i4 >> 5, c4 = i4 & 31;
        float4 a = S1[i4], g = S3[i4];
        __half2 lo = __floats2half2_rn(a.x / (1.f + __expf(-a.x)) * g.x,
                                       a.y / (1.f + __expf(-a.y)) * g.y);
        __half2 hi = __floats2half2_rn(a.z / (1.f + __expf(-a.z)) * g.z,
                                       a.w / (1.f + __expf(-a.w)) * g.w);
        __half2* hp = (__half2*)(g_hh + (size_t)(r0 + row) * NF + f0 + c4 * 4);
        hp[0] = lo; hp[1] = hi;
    }
#undef G1_ISSUE
}

// ---------------- GEMM2: out += w .* (hh W2^T), fp16 MMA ----------------
// grid (x=tiles, y=H/256); 8 warps 2m x 4n, warp tile 64x64
__global__ void __launch_bounds__(256, 1)
k_gemm2(float* __restrict__ out) {
    const int e = g_tile_expert[blockIdx.x];
    if (e < 0) return;
    extern __shared__ char smem[];
    const uint32_t sb = s2u(smem);
    const int tid = threadIdx.x, lane = tid & 31, wid = tid >> 5;
    const int r0 = blockIdx.x * BM, h0 = blockIdx.y * 256;

    int*   toks = (int*)smem;
    float* wgts = (float*)(smem + 512);
    if (tid < BM) {
        toks[tid] = g_slot_token[r0 + tid];
        wgts[tid] = g_slot_weight[r0 + tid];
    }
    __syncthreads();

    const __half* srcA[4]; uint32_t dstA[4];
    const __half* srcB[8]; uint32_t dstB[8];
#pragma unroll
    for (int i = 0; i < 4; i++) {
        int idx = tid + 256 * i, row = idx >> 3, q = idx & 7;
        srcA[i] = g_hh + (size_t)(r0 + row) * NF + q * 8;
        dstA[i] = sb + TILE0 + row * 128 + ((q ^ (row & 7)) << 4);
    }
#pragma unroll
    for (int i = 0; i < 8; i++) {
        int idx = tid + 256 * i, row = idx >> 3, q = idx & 7;   // rows 0..255
        srcB[i] = g_w2h + ((size_t)e * NH + h0 + row) * NF + q * 8;
        dstB[i] = sb + TILE0 + SA + row * 128 + ((q ^ (row & 7)) << 4);
    }

#define G2_ISSUE(S) do {                                                       \
        uint32_t _o = ((S) & 3) * STRIDE; int _k = (S) * KB;                   \
        _Pragma("unroll") for (int i = 0; i < 4; i++)                          \
            CP16(dstA[i] + _o, srcA[i] + _k, 16u);                             \
        _Pragma("unroll") for (int i = 0; i < 8; i++)                          \
            CP16(dstB[i] + _o, srcB[i] + _k, 16u);                             \
        CP_COMMIT();                                                           \
    } while (0)

    G2_ISSUE(0); G2_ISSUE(1); G2_ISSUE(2);

    const int wm = wid >> 2, wn = wid & 3;
    uint32_t mOff[4], nOff[4], swzA[4], swzB[4];
#pragma unroll
    for (int mf = 0; mf < 4; mf++) mOff[mf] = (wm * 64 + mf * 16 + (lane & 15)) * 128;
#pragma unroll
    for (int np = 0; np < 4; np++)
        nOff[np] = (wn * 64 + np * 16 + ((lane >> 4) << 3) + (lane & 7)) * 128;
#pragma unroll
    for (int ks = 0; ks < 4; ks++) {
        swzA[ks] = ((2 * ks + (lane >> 4)) ^ (lane & 7)) << 4;
        swzB[ks] = ((2 * ks + ((lane >> 3) & 1)) ^ (lane & 7)) << 4;
    }

    float acc[4][8][4] = {};

    for (int s = 0; s < NST2; s++) {
        CP_WAIT2();
        __syncthreads();
        if (s + 3 < NST2) G2_ISSUE(s + 3); else CP_COMMIT();
        const uint32_t aB = sb + TILE0 + (s & 3) * STRIDE;
        const uint32_t bB = aB + SA;
#pragma unroll
        for (int ks = 0; ks < 4; ks++) {
            uint32_t a[4][4], b[4][4];
#pragma unroll
            for (int mf = 0; mf < 4; mf++) LDSM4(a[mf], aB + mOff[mf] + swzA[ks]);
#pragma unroll
            for (int np = 0; np < 4; np++) LDSM4(b[np], bB + nOff[np] + swzB[ks]);
#pragma unroll
            for (int mf = 0; mf < 4; mf++)
#pragma unroll
                for (int nf = 0; nf < 8; nf++)
                    mma16(acc[mf][nf], a[mf], &b[nf >> 1][(nf & 1) * 2]);
        }
    }

    // epilogue: weighted scatter-add (exactly 2 adds/elem -> deterministic)
    const int rb = wm * 64, cb = wn * 64;
#pragma unroll
    for (int mf = 0; mf < 4; mf++)
#pragma unroll
        for (int nf = 0; nf < 8; nf++) {
            int r = rb + mf * 16 + (lane >> 2), c = cb + nf * 8 + (lane & 3) * 2;
            int t0 = toks[r];
            if (t0 >= 0) {
                float w = wgts[r];
                float* op = out + (size_t)t0 * NH + h0 + c;
                atomicAdd(op,     w * acc[mf][nf][0]);
                atomicAdd(op + 1, w * acc[mf][nf][1]);
            }
            int t1 = toks[r + 8];
            if (t1 >= 0) {
                float w = wgts[r + 8];
                float* op = out + (size_t)t1 * NH + h0 + c;
                atomicAdd(op,     w * acc[mf][nf][2]);
                atomicAdd(op + 1, w * acc[mf][nf][3]);
            }
        }
#undef G2_ISSUE
}

// ---------------- launch ----------------
extern "C" void kernel_launch(void* const* d_in, const int* in_sizes, int n_in,
                              void* d_out, int out_size) {
    const float* x  = (const float*)d_in[0];
    const float* gw = (const float*)d_in[1];
    const float* w1 = (const float*)d_in[2];
    const float* w2 = (const float*)d_in[3];
    const float* w3 = (const float*)d_in[4];
    float* out = (float*)d_out;

    static int configured = 0;
    if (!configured) {
        cudaFuncSetAttribute(k_gemm1, cudaFuncAttributeMaxDynamicSharedMemorySize, DSMEM);
        cudaFuncSetAttribute(k_gemm2, cudaFuncAttributeMaxDynamicSharedMemorySize, DSMEM);
        configured = 1;
    }

    __half *xh, *w1h, *w2h, *w3h;
    cudaGetSymbolAddress((void**)&xh,  g_xh);
    cudaGetSymbolAddress((void**)&w1h, g_w1h);
    cudaGetSymbolAddress((void**)&w2h, g_w2h);
    cudaGetSymbolAddress((void**)&w3h, g_w3h);

    const int n  = NT * NH;
    const int nx4 = NT * NH / 4;
    const int nw4 = NE * NF * NH / 4;
    k_zero<<<(n + 255) / 256, 256>>>(out, n);
    k_cvt<<<(nx4 + 255) / 256, 256>>>(x,  xh,  nx4);
    k_cvt<<<(nw4 + 255) / 256, 256>>>(w1, w1h, nw4);
    k_cvt<<<(nw4 + 255) / 256, 256>>>(w3, w3h, nw4);
    k_cvt<<<(nw4 + 255) / 256, 256>>>(w2, w2h, nw4);
    k_router<<<NT, 256>>>(x, gw);
    k_setup<<<1, 256>>>();
    k_scatter<<<(NSLOT + 255) / 256, 256>>>();
    k_gemm1<<<dim3(MAX_TILES, NF / 128), 256, DSMEM>>>();
    k_gemm2<<<dim3(MAX_TILES, NH / 256), 256, DSMEM>>>(out);
}

// round 8
// speedup vs baseline: 9.9005x; 1.0313x over previous
#include <cuda_runtime.h>
#include <cuda_fp16.h>
#include <math.h>
#include <stdint.h>

// ---------------- problem constants ----------------
#define NT 4096
#define NH 2048
#define NF 8192
#define NE 8

#define BM 128
#define KB 64                           // K halves per stage (128B rows)
#define NSLOT (2*NT)                    // 8192
#define MAX_TILES (NSLOT/BM + NE)       // 72
#define MAX_SLOTS (MAX_TILES*BM)        // 9216
#define NST1 (NH/KB)                    // 32
#define NST2 (NF/KB)                    // 128

// smem: toks/wgts in [0,1024), stages from 1024; stage stride 48KB, 4 stages
#define TILE0   1024
#define SA      16384                   // A tile 128x64 fp16
#define STRIDE  49152
#define DSMEM   (TILE0 + 4*STRIDE)      // 197632

// ---------------- device scratch ----------------
__device__ int    g_cnt[NE];
__device__ int    g_cursor[NE];
__device__ int    g_off[NE+1];
__device__ int    g_tok_expert[NSLOT];
__device__ float  g_tok_weight[NSLOT];
__device__ int    g_slot_token[MAX_SLOTS];
__device__ float  g_slot_weight[MAX_SLOTS];
__device__ int    g_tile_expert[MAX_TILES];
__device__ __half g_hh[(size_t)MAX_SLOTS * NF];      // 151 MB
__device__ __half g_xh[(size_t)NT * NH];             // 16 MB
__device__ __half g_w1h[(size_t)NE * NF * NH];       // 268 MB
__device__ __half g_w3h[(size_t)NE * NF * NH];       // 268 MB
__device__ __half g_w2h[(size_t)NE * NH * NF];       // 268 MB

// ---------------- PTX helpers ----------------
__device__ __forceinline__ uint32_t s2u(const void* p) {
    uint32_t a;
    asm("{ .reg .u64 t; cvta.to.shared.u64 t, %1; cvt.u32.u64 %0, t; }" : "=r"(a) : "l"(p));
    return a;
}
#define CP16(dst, src, sz)                                                     \
    asm volatile("cp.async.cg.shared.global [%0], [%1], 16, %2;"               \
                 :: "r"(dst), "l"(src), "r"(sz))
#define CP_COMMIT() asm volatile("cp.async.commit_group;" ::: "memory")
#define CP_WAIT2()  asm volatile("cp.async.wait_group 2;" ::: "memory")

#define LDSM4(r, a)                                                            \
    asm volatile("ldmatrix.sync.aligned.m8n8.x4.shared.b16 {%0,%1,%2,%3}, [%4];" \
        : "=r"((r)[0]), "=r"((r)[1]), "=r"((r)[2]), "=r"((r)[3]) : "r"(a))

__device__ __forceinline__ void mma16(float* d, const uint32_t* a, const uint32_t* b) {
    asm volatile(
        "mma.sync.aligned.m16n8k16.row.col.f32.f16.f16.f32 "
        "{%0,%1,%2,%3},{%4,%5,%6,%7},{%8,%9},{%0,%1,%2,%3};"
        : "+f"(d[0]), "+f"(d[1]), "+f"(d[2]), "+f"(d[3])
        : "r"(a[0]), "r"(a[1]), "r"(a[2]), "r"(a[3]), "r"(b[0]), "r"(b[1]));
}

__device__ __forceinline__ void cvt_store(const float4* src, __half2* dst, size_t i) {
    float4 v = src[i];
    dst[2 * i]     = __floats2half2_rn(v.x, v.y);
    dst[2 * i + 1] = __floats2half2_rn(v.z, v.w);
}

// ---------------- prep: zero out + reset counters + cvt w1/w3/x ----------------
#define N4_OUT  ((size_t)NT * NH / 4)          // 2,097,152
#define N4_W    ((size_t)NE * NF * NH / 4)     // 33,554,432
#define PREP_TOTAL (N4_OUT + 2 * N4_W + N4_OUT)

__global__ void k_prep(const float* __restrict__ x, const float* __restrict__ w1,
                       const float* __restrict__ w3, float* __restrict__ out) {
    size_t i = (size_t)blockIdx.x * blockDim.x + threadIdx.x;
    if (i < 8) g_cnt[i] = 0;
    if (i < N4_OUT) {
        ((float4*)out)[i] = make_float4(0.f, 0.f, 0.f, 0.f);
        return;
    }
    i -= N4_OUT;
    if (i < N4_W) { cvt_store((const float4*)w1, (__half2*)g_w1h, i); return; }
    i -= N4_W;
    if (i < N4_W) { cvt_store((const float4*)w3, (__half2*)g_w3h, i); return; }
    i -= N4_W;
    if (i < N4_OUT) cvt_store((const float4*)x, (__half2*)g_xh, i);
}

// ---------------- router ----------------
__global__ void k_router(const float* __restrict__ x, const float* __restrict__ gw) {
    const int t = blockIdx.x, tid = threadIdx.x;
    float acc[NE];
#pragma unroll
    for (int e = 0; e < NE; e++) acc[e] = 0.f;
    const float* xr = x + (size_t)t * NH;
    for (int h = tid; h < NH; h += 256) {
        float xv = xr[h];
#pragma unroll
        for (int e = 0; e < NE; e++) acc[e] += xv * gw[e * NH + h];
    }
    __shared__ float part[NE][256];
#pragma unroll
    for (int e = 0; e < NE; e++) part[e][tid] = acc[e];
    __syncthreads();
    if (tid < NE) {
        float s = 0.f;
        for (int i = 0; i < 256; i++) s += part[tid][i];
        part[tid][0] = s;
    }
    __syncthreads();
    if (tid == 0) {
        float l[NE];
#pragma unroll
        for (int e = 0; e < NE; e++) l[e] = part[e][0];
        int i0 = 0;
#pragma unroll
        for (int e = 1; e < NE; e++) if (l[e] > l[i0]) i0 = e;
        int i1 = -1;
#pragma unroll
        for (int e = 0; e < NE; e++)
            if (e != i0 && (i1 < 0 || l[e] > l[i1])) i1 = e;
        float w0 = 1.f / (1.f + expf(l[i1] - l[i0]));
        g_tok_expert[2 * t] = i0;  g_tok_expert[2 * t + 1] = i1;
        g_tok_weight[2 * t] = w0;  g_tok_weight[2 * t + 1] = 1.f - w0;
        atomicAdd(&g_cnt[i0], 1);
        atomicAdd(&g_cnt[i1], 1);
    }
}

__global__ void k_setup() {
    __shared__ int soff[NE + 1];
    const int tid = threadIdx.x;
    if (tid == 0) {
        int o = 0;
        for (int e = 0; e < NE; e++) {
            soff[e] = o; g_off[e] = o; g_cursor[e] = 0;
            o += ((g_cnt[e] + BM - 1) / BM) * BM;
        }
        soff[NE] = o; g_off[NE] = o;
    }
    __syncthreads();
    const int ntiles = soff[NE] / BM;
    for (int i = tid; i < MAX_TILES; i += blockDim.x) {
        int ex = -1;
        if (i < ntiles) {
            int r = i * BM;
            for (int e = 0; e < NE; e++)
                if (r >= soff[e] && r < soff[e + 1]) ex = e;
        }
        g_tile_expert[i] = ex;
    }
    for (int i = tid; i < MAX_SLOTS; i += blockDim.x) {
        g_slot_token[i]  = -1;
        g_slot_weight[i] = 0.f;
    }
}

__global__ void k_scatter() {
    int i = blockIdx.x * blockDim.x + threadIdx.x;
    if (i >= NSLOT) return;
    int e = g_tok_expert[i];
    int pos = atomicAdd(&g_cursor[e], 1);
    int s = g_off[e] + pos;
    g_slot_token[s]  = i >> 1;
    g_slot_weight[s] = g_tok_weight[i];
}

// ---------------- GEMM1 (+interleaved w2 conversion blocks) ----------------
// grid (x=MAX_TILES, y=72). y%9==8 -> w2 cvt slice; else f-block = y - y/9.
__global__ void __launch_bounds__(256, 1)
k_gemm1(const float* __restrict__ w2src) {
    const int tid = threadIdx.x;
    const int y = blockIdx.y;

    if (y % 9 == 8) {                   // --- w2 fp32->fp16 conversion block ---
        const size_t lin   = ((size_t)(y / 9) * MAX_TILES + blockIdx.x) * 256 + tid;
        const size_t strid = (size_t)8 * MAX_TILES * 256;
        const float4* src = (const float4*)w2src;
        __half2* dst = (__half2*)g_w2h;
        for (size_t i = lin; i < N4_W; i += strid) cvt_store(src, dst, i);
        return;
    }

    const int e = g_tile_expert[blockIdx.x];
    if (e < 0) return;
    extern __shared__ char smem[];
    const uint32_t sb = s2u(smem);
    const int lane = tid & 31, wid = tid >> 5;
    const int r0 = blockIdx.x * BM, f0 = (y - y / 9) * 128;

    int* toks = (int*)smem;
    if (tid < BM) toks[tid] = g_slot_token[r0 + tid];
    __syncthreads();

    const __half* srcA[4]; uint32_t dstA[4], szA[4];
    const __half* srcB1[4]; const __half* srcB3[4]; uint32_t dstB[4];
#pragma unroll
    for (int i = 0; i < 4; i++) {
        int idx = tid + 256 * i, row = idx >> 3, q = idx & 7;
        int t = toks[row];
        szA[i]  = (t >= 0) ? 16u : 0u;
        srcA[i] = g_xh + (size_t)(t >= 0 ? t : 0) * NH + q * 8;
        uint32_t sw = row * 128 + ((q ^ (row & 7)) << 4);
        dstA[i] = sb + TILE0 + sw;
        srcB1[i] = g_w1h + ((size_t)e * NF + f0 + row) * NH + q * 8;
        srcB3[i] = g_w3h + ((size_t)e * NF + f0 + row) * NH + q * 8;
        dstB[i]  = sb + TILE0 + SA + sw;
    }

#define G1_ISSUE(S) do {                                                       \
        uint32_t _o = ((S) & 3) * STRIDE; int _k = (S) * KB;                   \
        _Pragma("unroll") for (int i = 0; i < 4; i++)                          \
            CP16(dstA[i] + _o, srcA[i] + _k, szA[i]);                          \
        _Pragma("unroll") for (int i = 0; i < 4; i++)                          \
            CP16(dstB[i] + _o, srcB1[i] + _k, 16u);                            \
        _Pragma("unroll") for (int i = 0; i < 4; i++)                          \
            CP16(dstB[i] + _o + SA, srcB3[i] + _k, 16u);                       \
        CP_COMMIT();                                                           \
    } while (0)

    G1_ISSUE(0); G1_ISSUE(1); G1_ISSUE(2);

    const int mat = wid >> 2, wm = (wid >> 1) & 1, wn = wid & 1;
    uint32_t mOff[4], nOff[4], swzA[4], swzB[4];
#pragma unroll
    for (int mf = 0; mf < 4; mf++) mOff[mf] = (wm * 64 + mf * 16 + (lane & 15)) * 128;
#pragma unroll
    for (int np = 0; np < 4; np++)
        nOff[np] = (wn * 64 + np * 16 + ((lane >> 4) << 3) + (lane & 7)) * 128;
#pragma unroll
    for (int ks = 0; ks < 4; ks++) {
        swzA[ks] = ((2 * ks + (lane >> 4)) ^ (lane & 7)) << 4;
        swzB[ks] = ((2 * ks + ((lane >> 3) & 1)) ^ (lane & 7)) << 4;
    }

    float acc[4][8][4] = {};

    for (int s = 0; s < NST1; s++) {
        CP_WAIT2();
        __syncthreads();
        if (s + 3 < NST1) G1_ISSUE(s + 3); else CP_COMMIT();
        const uint32_t aB = sb + TILE0 + (s & 3) * STRIDE;
        const uint32_t bB = aB + SA + mat * SA;
#pragma unroll
        for (int ks = 0; ks < 4; ks++) {
            uint32_t a[4][4], b[4][4];
#pragma unroll
            for (int mf = 0; mf < 4; mf++) LDSM4(a[mf], aB + mOff[mf] + swzA[ks]);
#pragma unroll
            for (int np = 0; np < 4; np++) LDSM4(b[np], bB + nOff[np] + swzB[ks]);
#pragma unroll
            for (int mf = 0; mf < 4; mf++)
#pragma unroll
                for (int nf = 0; nf < 8; nf++)
                    mma16(acc[mf][nf], a[mf], &b[nf >> 1][(nf & 1) * 2]);
        }
    }
    __syncthreads();

    float* Sg = (float*)(smem + TILE0 + mat * 65536);
    const int rb = wm * 64, cb = wn * 64;
#pragma unroll
    for (int mf = 0; mf < 4; mf++)
#pragma unroll
        for (int nf = 0; nf < 8; nf++) {
            int r = rb + mf * 16 + (lane >> 2), c = cb + nf * 8 + (lane & 3) * 2;
            Sg[r * 128 + c]             = acc[mf][nf][0];
            Sg[r * 128 + c + 1]         = acc[mf][nf][1];
            Sg[(r + 8) * 128 + c]       = acc[mf][nf][2];
            Sg[(r + 8) * 128 + c + 1]   = acc[mf][nf][3];
        }
    __syncthreads();
    const float4* S1 = (const float4*)(smem + TILE0);
    const float4* S3 = (const float4*)(smem + TILE0 + 65536);
#pragma unroll
    for (int k2 = 0; k2 < 16; k2++) {
        int i4 = tid + 256 * k2;
        int row = i4 >> 5, c4 = i4 & 31;
        float4 a = S1[i4], g = S3[i4];
        __half2 lo = __floats2half2_rn(a.x / (1.f + __expf(-a.x)) * g.x,
                                       a.y / (1.f + __expf(-a.y)) * g.y);
        __half2 hi = __floats2half2_rn(a.z / (1.f + __expf(-a.z)) * g.z,
                                       a.w / (1.f + __expf(-a.w)) * g.w);
        __half2* hp = (__half2*)(g_hh + (size_t)(r0 + row) * NF + f0 + c4 * 4);
        hp[0] = lo; hp[1] = hi;
    }
#undef G1_ISSUE
}

// ---------------- GEMM2: out += w .* (hh W2^T), fp16 MMA ----------------
__global__ void __launch_bounds__(256, 1)
k_gemm2(float* __restrict__ out) {
    const int e = g_tile_expert[blockIdx.x];
    if (e < 0) return;
    extern __shared__ char smem[];
    const uint32_t sb = s2u(smem);
    const int tid = threadIdx.x, lane = tid & 31, wid = tid >> 5;
    const int r0 = blockIdx.x * BM, h0 = blockIdx.y * 256;

    int*   toks = (int*)smem;
    float* wgts = (float*)(smem + 512);
    if (tid < BM) {
        toks[tid] = g_slot_token[r0 + tid];
        wgts[tid] = g_slot_weight[r0 + tid];
    }
    __syncthreads();

    const __half* srcA[4]; uint32_t dstA[4];
    const __half* srcB[8]; uint32_t dstB[8];
#pragma unroll
    for (int i = 0; i < 4; i++) {
        int idx = tid + 256 * i, row = idx >> 3, q = idx & 7;
        srcA[i] = g_hh + (size_t)(r0 + row) * NF + q * 8;
        dstA[i] = sb + TILE0 + row * 128 + ((q ^ (row & 7)) << 4);
    }
#pragma unroll
    for (int i = 0; i < 8; i++) {
        int idx = tid + 256 * i, row = idx >> 3, q = idx & 7;
        srcB[i] = g_w2h + ((size_t)e * NH + h0 + row) * NF + q * 8;
        dstB[i] = sb + TILE0 + SA + row * 128 + ((q ^ (row & 7)) << 4);
    }

#define G2_ISSUE(S) do {                                                       \
        uint32_t _o = ((S) & 3) * STRIDE; int _k = (S) * KB;                   \
        _Pragma("unroll") for (int i = 0; i < 4; i++)                          \
            CP16(dstA[i] + _o, srcA[i] + _k, 16u);                             \
        _Pragma("unroll") for (int i = 0; i < 8; i++)                          \
            CP16(dstB[i] + _o, srcB[i] + _k, 16u);                             \
        CP_COMMIT();                                                           \
    } while (0)

    G2_ISSUE(0); G2_ISSUE(1); G2_ISSUE(2);

    const int wm = wid >> 2, wn = wid & 3;
    uint32_t mOff[4], nOff[4], swzA[4], swzB[4];
#pragma unroll
    for (int mf = 0; mf < 4; mf++) mOff[mf] = (wm * 64 + mf * 16 + (lane & 15)) * 128;
#pragma unroll
    for (int np = 0; np < 4; np++)
        nOff[np] = (wn * 64 + np * 16 + ((lane >> 4) << 3) + (lane & 7)) * 128;
#pragma unroll
    for (int ks = 0; ks < 4; ks++) {
        swzA[ks] = ((2 * ks + (lane >> 4)) ^ (lane & 7)) << 4;
        swzB[ks] = ((2 * ks + ((lane >> 3) & 1)) ^ (lane & 7)) << 4;
    }

    float acc[4][8][4] = {};

    for (int s = 0; s < NST2; s++) {
        CP_WAIT2();
        __syncthreads();
        if (s + 3 < NST2) G2_ISSUE(s + 3); else CP_COMMIT();
        const uint32_t aB = sb + TILE0 + (s & 3) * STRIDE;
        const uint32_t bB = aB + SA;
#pragma unroll
        for (int ks = 0; ks < 4; ks++) {
            uint32_t a[4][4], b[4][4];
#pragma unroll
            for (int mf = 0; mf < 4; mf++) LDSM4(a[mf], aB + mOff[mf] + swzA[ks]);
#pragma unroll
            for (int np = 0; np < 4; np++) LDSM4(b[np], bB + nOff[np] + swzB[ks]);
#pragma unroll
            for (int mf = 0; mf < 4; mf++)
#pragma unroll
                for (int nf = 0; nf < 8; nf++)
                    mma16(acc[mf][nf], a[mf], &b[nf >> 1][(nf & 1) * 2]);
        }
    }

    const int rb = wm * 64, cb = wn * 64;
#pragma unroll
    for (int mf = 0; mf < 4; mf++)
#pragma unroll
        for (int nf = 0; nf < 8; nf++) {
            int r = rb + mf * 16 + (lane >> 2), c = cb + nf * 8 + (lane & 3) * 2;
            int t0 = toks[r];
            if (t0 >= 0) {
                float w = wgts[r];
                float* op = out + (size_t)t0 * NH + h0 + c;
                atomicAdd(op,     w * acc[mf][nf][0]);
                atomicAdd(op + 1, w * acc[mf][nf][1]);
            }
            int t1 = toks[r + 8];
            if (t1 >= 0) {
                float w = wgts[r + 8];
                float* op = out + (size_t)t1 * NH + h0 + c;
                atomicAdd(op,     w * acc[mf][nf][2]);
                atomicAdd(op + 1, w * acc[mf][nf][3]);
            }
        }
#undef G2_ISSUE
}

// ---------------- launch ----------------
extern "C" void kernel_launch(void* const* d_in, const int* in_sizes, int n_in,
                              void* d_out, int out_size) {
    const float* x  = (const float*)d_in[0];
    const float* gw = (const float*)d_in[1];
    const float* w1 = (const float*)d_in[2];
    const float* w2 = (const float*)d_in[3];
    const float* w3 = (const float*)d_in[4];
    float* out = (float*)d_out;

    static int configured = 0;
    if (!configured) {
        cudaFuncSetAttribute(k_gemm1, cudaFuncAttributeMaxDynamicSharedMemorySize, DSMEM);
        cudaFuncSetAttribute(k_gemm2, cudaFuncAttributeMaxDynamicSharedMemorySize, DSMEM);
        configured = 1;
    }

    const size_t prep_blocks = (PREP_TOTAL + 255) / 256;
    k_prep<<<(unsigned)prep_blocks, 256>>>(x, w1, w3, out);
    k_router<<<NT, 256>>>(x, gw);
    k_setup<<<1, 256>>>();
    k_scatter<<<(NSLOT + 255) / 256, 256>>>();
    k_gemm1<<<dim3(MAX_TILES, 72), 256, DSMEM>>>(w2);   // 64 gemm y + 8 cvt y
    k_gemm2<<<dim3(MAX_TILES, NH / 256), 256, DSMEM>>>(out);
}